// round 1
// baseline (speedup 1.0000x reference)
#include <cuda_runtime.h>
#include <cuda_bf16.h>

#define Bb 16
#define Nn 2048
#define Cc 512
#define K3 (3*Cc)   // 1536

// ------------------- scratch (device globals; no allocations) -------------------
__device__ float g_xc  [Bb*Cc*Nn];   // transposed input  [B,C,N]
__device__ float g_q   [Bb*Cc*Nn];
__device__ float g_k   [Bb*Cc*Nn];
__device__ float g_v   [Bb*Cc*Nn];
__device__ float g_attn[Bb*Cc*Cc];
__device__ float g_o   [Bb*Cc*Nn];
__device__ float g_weff[3*(size_t)Cc*K3];  // per-branch effective k=3 weights [o][t*C+c]

// ------------------- transpose x [B,N,C] -> xc [B,C,N] -------------------
__global__ __launch_bounds__(256) void transpose_x(const float* __restrict__ x) {
    __shared__ float tile[32][33];
    int b  = blockIdx.z;
    int n0 = blockIdx.x * 32;
    int c0 = blockIdx.y * 32;
    int tx = threadIdx.x, ty = threadIdx.y;   // 32 x 8
    #pragma unroll
    for (int i = 0; i < 32; i += 8)
        tile[ty + i][tx] = x[(size_t)b*Nn*Cc + (size_t)(n0 + ty + i)*Cc + c0 + tx];
    __syncthreads();
    #pragma unroll
    for (int i = 0; i < 32; i += 8)
        g_xc[(size_t)b*Cc*Nn + (size_t)(c0 + ty + i)*Nn + n0 + tx] = tile[tx][ty + i];
}

// ------------------- Weff[o, t*C + c] = sum_i w3[o,i,t] * w1[i,c] -------------------
// grid: (C/64 over c, C/64 over o, 3 over t); one launch per branch
__global__ __launch_bounds__(256) void weff_kernel(const float* __restrict__ w1,
                                                   const float* __restrict__ w3,
                                                   int br) {
    int t  = blockIdx.z;
    int n0 = blockIdx.x * 64;   // c
    int m0 = blockIdx.y * 64;   // o
    __shared__ float As[64][17];
    __shared__ float Bs[16][64];
    int tid = threadIdx.x;
    int tx = tid & 15, ty = tid >> 4;
    float acc[4][4] = {};
    for (int k0 = 0; k0 < Cc; k0 += 16) {
        {   // A: w3 slice (stride-3 along i)
            int kk = tid & 15, mmb = tid >> 4;
            #pragma unroll
            for (int j = 0; j < 4; j++) {
                int mm = mmb + j*16;
                As[mm][kk] = w3[(size_t)(m0+mm)*Cc*3 + (size_t)(k0+kk)*3 + t];
            }
        }
        {   // B: w1 row-major
            int nn = tid & 63, kkb = tid >> 6;
            #pragma unroll
            for (int j = 0; j < 4; j++) {
                int kk = kkb + j*4;
                Bs[kk][nn] = w1[(size_t)(k0+kk)*Cc + n0 + nn];
            }
        }
        __syncthreads();
        #pragma unroll
        for (int kk = 0; kk < 16; kk++) {
            float a[4];
            #pragma unroll
            for (int i = 0; i < 4; i++) a[i] = As[ty*4+i][kk];
            float4 bv = *(const float4*)&Bs[kk][tx*4];
            float bf[4] = {bv.x, bv.y, bv.z, bv.w};
            #pragma unroll
            for (int i = 0; i < 4; i++)
                #pragma unroll
                for (int j = 0; j < 4; j++) acc[i][j] += a[i]*bf[j];
        }
        __syncthreads();
    }
    float* wf = g_weff + (size_t)br*Cc*K3;
    #pragma unroll
    for (int i = 0; i < 4; i++) {
        int o = m0 + ty*4 + i;
        #pragma unroll
        for (int j = 0; j < 4; j++) {
            int c = n0 + tx*4 + j;
            wf[(size_t)o*K3 + t*Cc + c] = acc[i][j];
        }
    }
}

// ------------------- branch GEMM: out[b,o,n] = sum_{k=(t,c)} Weff[o,k] * xc[b,c,wrap(n+t-1)] ---
// grid: (N/64, C/64, B); one launch per branch (which: 0=q,1=k,2=v)
__global__ __launch_bounds__(256) void conv_gemm(int which) {
    int b  = blockIdx.z;
    const float* X  = g_xc + (size_t)b*Cc*Nn;
    const float* wf = g_weff + (size_t)which*Cc*K3;
    float* out = (which == 0 ? g_q : which == 1 ? g_k : g_v) + (size_t)b*Cc*Nn;
    int n0 = blockIdx.x * 64;
    int m0 = blockIdx.y * 64;
    __shared__ float As[64][17];
    __shared__ float Bs[16][64];
    int tid = threadIdx.x;
    int tx = tid & 15, ty = tid >> 4;
    float acc[4][4] = {};
    for (int k0 = 0; k0 < K3; k0 += 16) {
        {
            int kk = tid & 15, mmb = tid >> 4;
            #pragma unroll
            for (int j = 0; j < 4; j++) {
                int mm = mmb + j*16;
                As[mm][kk] = wf[(size_t)(m0+mm)*K3 + k0 + kk];
            }
        }
        {
            int nn = tid & 63, kkb = tid >> 6;
            #pragma unroll
            for (int j = 0; j < 4; j++) {
                int kk = kkb + j*4;
                int kg = k0 + kk;
                int t  = kg >> 9;       // /512
                int c  = kg & 511;
                int col = n0 + nn + t - 1;
                if (col < 0) col += Nn; else if (col >= Nn) col -= Nn;
                Bs[kk][nn] = X[(size_t)c*Nn + col];
            }
        }
        __syncthreads();
        #pragma unroll
        for (int kk = 0; kk < 16; kk++) {
            float a[4];
            #pragma unroll
            for (int i = 0; i < 4; i++) a[i] = As[ty*4+i][kk];
            float4 bv = *(const float4*)&Bs[kk][tx*4];
            float bf[4] = {bv.x, bv.y, bv.z, bv.w};
            #pragma unroll
            for (int i = 0; i < 4; i++)
                #pragma unroll
                for (int j = 0; j < 4; j++) acc[i][j] += a[i]*bf[j];
        }
        __syncthreads();
    }
    #pragma unroll
    for (int i = 0; i < 4; i++) {
        int m = m0 + ty*4 + i;
        #pragma unroll
        for (int j = 0; j < 4; j++)
            out[(size_t)m*Nn + n0 + tx*4 + j] = acc[i][j];
    }
}

// ------------------- scores: S[b,c,d] = (1/C) * sum_n q[b,c,n] * k[b,d,n] -------------------
// grid: (C/64 over d, C/64 over c, B)
__global__ __launch_bounds__(256) void scores_gemm() {
    int b = blockIdx.z;
    const float* Q = g_q + (size_t)b*Cc*Nn;
    const float* Kt = g_k + (size_t)b*Cc*Nn;
    int n0 = blockIdx.x * 64;   // d
    int m0 = blockIdx.y * 64;   // c
    __shared__ float As[64][17];
    __shared__ float Bs[16][65];
    int tid = threadIdx.x;
    int tx = tid & 15, ty = tid >> 4;
    float acc[4][4] = {};
    for (int k0 = 0; k0 < Nn; k0 += 16) {
        {
            int kk = tid & 15, mmb = tid >> 4;
            #pragma unroll
            for (int j = 0; j < 4; j++) {
                int mm = mmb + j*16;
                As[mm][kk] = Q[(size_t)(m0+mm)*Nn + k0 + kk];
            }
        }
        {
            int kk = tid & 15, nnb = tid >> 4;
            #pragma unroll
            for (int j = 0; j < 4; j++) {
                int nn = nnb + j*16;
                Bs[kk][nn] = Kt[(size_t)(n0+nn)*Nn + k0 + kk];
            }
        }
        __syncthreads();
        #pragma unroll
        for (int kk = 0; kk < 16; kk++) {
            float a[4], bf[4];
            #pragma unroll
            for (int i = 0; i < 4; i++) a[i] = As[ty*4+i][kk];
            #pragma unroll
            for (int j = 0; j < 4; j++) bf[j] = Bs[kk][tx*4+j];
            #pragma unroll
            for (int i = 0; i < 4; i++)
                #pragma unroll
                for (int j = 0; j < 4; j++) acc[i][j] += a[i]*bf[j];
        }
        __syncthreads();
    }
    const float scale = 1.0f / (float)Cc;
    #pragma unroll
    for (int i = 0; i < 4; i++) {
        int m = m0 + ty*4 + i;
        #pragma unroll
        for (int j = 0; j < 4; j++)
            g_attn[(size_t)b*Cc*Cc + (size_t)m*Cc + n0 + tx*4 + j] = acc[i][j] * scale;
    }
}

// ------------------- softmax over rows of g_attn (rows of length C=512) -------------------
__global__ __launch_bounds__(256) void softmax_kernel() {
    int row = blockIdx.x;   // b*C + c
    float* p = g_attn + (size_t)row*Cc;
    int tid = threadIdx.x;
    float v0 = p[tid], v1 = p[tid + 256];
    float m = fmaxf(v0, v1);
    __shared__ float red[8];
    #pragma unroll
    for (int o = 16; o > 0; o >>= 1) m = fmaxf(m, __shfl_xor_sync(0xffffffffu, m, o));
    if ((tid & 31) == 0) red[tid >> 5] = m;
    __syncthreads();
    float mm = red[0];
    #pragma unroll
    for (int i = 1; i < 8; i++) mm = fmaxf(mm, red[i]);
    float e0 = __expf(v0 - mm), e1 = __expf(v1 - mm);
    float s = e0 + e1;
    #pragma unroll
    for (int o = 16; o > 0; o >>= 1) s += __shfl_xor_sync(0xffffffffu, s, o);
    __syncthreads();
    if ((tid & 31) == 0) red[tid >> 5] = s;
    __syncthreads();
    float ss = 0.f;
    #pragma unroll
    for (int i = 0; i < 8; i++) ss += red[i];
    float inv = 1.0f / ss;
    p[tid] = e0 * inv;
    p[tid + 256] = e1 * inv;
}

// ------------------- O[b] = P[b] (C x C) * V[b] (C x N) -------------------
// grid: (N/64, C/64, B)
__global__ __launch_bounds__(256) void pv_gemm() {
    int b = blockIdx.z;
    const float* P = g_attn + (size_t)b*Cc*Cc;
    const float* V = g_v    + (size_t)b*Cc*Nn;
    float* O = g_o + (size_t)b*Cc*Nn;
    int n0 = blockIdx.x * 64;
    int m0 = blockIdx.y * 64;
    __shared__ float As[64][17];
    __shared__ float Bs[16][64];
    int tid = threadIdx.x;
    int tx = tid & 15, ty = tid >> 4;
    float acc[4][4] = {};
    for (int k0 = 0; k0 < Cc; k0 += 16) {
        {
            int kk = tid & 15, mmb = tid >> 4;
            #pragma unroll
            for (int j = 0; j < 4; j++) {
                int mm = mmb + j*16;
                As[mm][kk] = P[(size_t)(m0+mm)*Cc + k0 + kk];
            }
        }
        {
            int nn = tid & 63, kkb = tid >> 6;
            #pragma unroll
            for (int j = 0; j < 4; j++) {
                int kk = kkb + j*4;
                Bs[kk][nn] = V[(size_t)(k0+kk)*Nn + n0 + nn];
            }
        }
        __syncthreads();
        #pragma unroll
        for (int kk = 0; kk < 16; kk++) {
            float a[4];
            #pragma unroll
            for (int i = 0; i < 4; i++) a[i] = As[ty*4+i][kk];
            float4 bv = *(const float4*)&Bs[kk][tx*4];
            float bf[4] = {bv.x, bv.y, bv.z, bv.w};
            #pragma unroll
            for (int i = 0; i < 4; i++)
                #pragma unroll
                for (int j = 0; j < 4; j++) acc[i][j] += a[i]*bf[j];
        }
        __syncthreads();
    }
    #pragma unroll
    for (int i = 0; i < 4; i++) {
        int m = m0 + ty*4 + i;
        #pragma unroll
        for (int j = 0; j < 4; j++)
            O[(size_t)m*Nn + n0 + tx*4 + j] = acc[i][j];
    }
}

// ------------------- y[b,n,o] = sum_c wproj[o,c] * O[b,c,n] + bproj[o] -------------------
// grid: (C/64 over o, N/64 over n, B). Rows m = n, cols = o.
__global__ __launch_bounds__(256) void proj_gemm(const float* __restrict__ wproj,
                                                 const float* __restrict__ bproj,
                                                 float* __restrict__ y) {
    int b = blockIdx.z;
    const float* O = g_o + (size_t)b*Cc*Nn;
    int n0 = blockIdx.x * 64;   // o
    int m0 = blockIdx.y * 64;   // n
    __shared__ float As[64][17];
    __shared__ float Bs[16][65];
    int tid = threadIdx.x;
    int tx = tid & 15, ty = tid >> 4;
    float acc[4][4] = {};
    for (int k0 = 0; k0 < Cc; k0 += 16) {
        {   // A[n][c] = O[c*N + n]  (contiguous along n)
            int mm = tid & 63, kkb = tid >> 6;
            #pragma unroll
            for (int j = 0; j < 4; j++) {
                int kk = kkb + j*4;
                As[mm][kk] = O[(size_t)(k0+kk)*Nn + m0 + mm];
            }
        }
        {   // B[c][o] = wproj[o*C + c]  (contiguous along c)
            int kk = tid & 15, nnb = tid >> 4;
            #pragma unroll
            for (int j = 0; j < 4; j++) {
                int nn = nnb + j*16;
                Bs[kk][nn] = wproj[(size_t)(n0+nn)*Cc + k0 + kk];
            }
        }
        __syncthreads();
        #pragma unroll
        for (int kk = 0; kk < 16; kk++) {
            float a[4], bf[4];
            #pragma unroll
            for (int i = 0; i < 4; i++) a[i] = As[ty*4+i][kk];
            #pragma unroll
            for (int j = 0; j < 4; j++) bf[j] = Bs[kk][tx*4+j];
            #pragma unroll
            for (int i = 0; i < 4; i++)
                #pragma unroll
                for (int j = 0; j < 4; j++) acc[i][j] += a[i]*bf[j];
        }
        __syncthreads();
    }
    #pragma unroll
    for (int i = 0; i < 4; i++) {
        int m = m0 + ty*4 + i;   // n
        #pragma unroll
        for (int j = 0; j < 4; j++) {
            int o = n0 + tx*4 + j;
            y[(size_t)b*Nn*Cc + (size_t)m*Cc + o] = acc[i][j] + bproj[o];
        }
    }
}

// ------------------- launch -------------------
extern "C" void kernel_launch(void* const* d_in, const int* in_sizes, int n_in,
                              void* d_out, int out_size) {
    const float* x     = (const float*)d_in[0];
    const float* w1q   = (const float*)d_in[1];
    const float* w3q   = (const float*)d_in[2];
    const float* w1k   = (const float*)d_in[3];
    const float* w3k   = (const float*)d_in[4];
    const float* w1v   = (const float*)d_in[5];
    const float* w3v   = (const float*)d_in[6];
    const float* wproj = (const float*)d_in[7];
    const float* bproj = (const float*)d_in[8];
    float* y = (float*)d_out;

    transpose_x<<<dim3(Nn/32, Cc/32, Bb), dim3(32, 8)>>>(x);

    weff_kernel<<<dim3(Cc/64, Cc/64, 3), 256>>>(w1q, w3q, 0);
    weff_kernel<<<dim3(Cc/64, Cc/64, 3), 256>>>(w1k, w3k, 1);
    weff_kernel<<<dim3(Cc/64, Cc/64, 3), 256>>>(w1v, w3v, 2);

    conv_gemm<<<dim3(Nn/64, Cc/64, Bb), 256>>>(0);
    conv_gemm<<<dim3(Nn/64, Cc/64, Bb), 256>>>(1);
    conv_gemm<<<dim3(Nn/64, Cc/64, Bb), 256>>>(2);

    scores_gemm<<<dim3(Cc/64, Cc/64, Bb), 256>>>();
    softmax_kernel<<<Bb*Cc, 256>>>();
    pv_gemm<<<dim3(Nn/64, Cc/64, Bb), 256>>>();
    proj_gemm<<<dim3(Cc/64, Nn/64, Bb), 256>>>(wproj, bproj, y);
}

// round 3
// speedup vs baseline: 2.5700x; 2.5700x over previous
#include <cuda_runtime.h>
#include <cuda_fp16.h>
#include <cstdint>

#define Bb 16
#define Nn 2048
#define Cc 512
#define K3 1536

// ---------------- device scratch (no allocations) ----------------
__device__ float  g_w3t [9*512*512];          // [br*3+t][o][i]
__device__ float  g_weff[1536*1536];          // [br*512+o][t*512+c]
__device__ __half g_wh [1536*1536];
__device__ __half g_wl [1536*1536];
__device__ __half g_wph[512*512];
__device__ __half g_wpl[512*512];
__device__ __half g_xh [50331648];            // [b][n][t*512+c]
__device__ __half g_xl [50331648];
__device__ __half g_qkvh[50331648];           // [b][3C][N]
__device__ __half g_qkvl[50331648];
__device__ __half g_vth[16777216];            // [b][n][d]
__device__ __half g_vtl[16777216];
__device__ float  g_S  [4194304];             // [b][c][d]
__device__ __half g_ph [4194304];
__device__ __half g_pl [4194304];
__device__ __half g_oth[16777216];            // [b][n][c]
__device__ __half g_otl[16777216];

// ---------------- PTX helpers (sm_80-era only; no tcgen05) ----------------
__device__ __forceinline__ uint32_t s2u(const void* p){
    uint32_t a; asm("{ .reg .u64 t; cvta.to.shared.u64 t, %1; cvt.u32.u64 %0, t; }" : "=r"(a) : "l"(p)); return a;
}
__device__ __forceinline__ void cpa16(uint32_t d, const void* s){
    asm volatile("cp.async.cg.shared.global [%0], [%1], 16;" :: "r"(d), "l"(s));
}
__device__ __forceinline__ void cp_commit(){ asm volatile("cp.async.commit_group;"); }
__device__ __forceinline__ void cp_wait1(){ asm volatile("cp.async.wait_group 1;"); }
__device__ __forceinline__ void cp_wait0(){ asm volatile("cp.async.wait_group 0;"); }
__device__ __forceinline__ void ldsm4(uint32_t& r0, uint32_t& r1, uint32_t& r2, uint32_t& r3, uint32_t a){
    asm volatile("ldmatrix.sync.aligned.m8n8.x4.shared.b16 {%0,%1,%2,%3}, [%4];"
        : "=r"(r0), "=r"(r1), "=r"(r2), "=r"(r3) : "r"(a));
}
__device__ __forceinline__ void mma16816(float* d, const uint32_t* a, uint32_t b0, uint32_t b1){
    asm volatile("mma.sync.aligned.m16n8k16.row.col.f32.f16.f16.f32 "
        "{%0,%1,%2,%3}, {%4,%5,%6,%7}, {%8,%9}, {%0,%1,%2,%3};"
        : "+f"(d[0]), "+f"(d[1]), "+f"(d[2]), "+f"(d[3])
        : "r"(a[0]), "r"(a[1]), "r"(a[2]), "r"(a[3]), "r"(b0), "r"(b1));
}

// ---------------- generic HMMA f16x3 GEMM ----------------
// D[m, n] = sum_k (Ah+Al)[m,k] * (Bh+Bl)[n,k]   (Al*Bl dropped)
// CTA tile 128x128, warp tile 32x64 (warps 4M x 2N), K stage 32, double-buffered.
struct GArgs {
    const __half* Ah; const __half* Al;
    const __half* Bh; const __half* Bl;
    long long sA, sB, sC;       // per-batch element strides
    int lda, ldb, ldc, K;
    float* Cf; __half* Ch; __half* Cl;   // out: fp32 OR split half
    const float* bias;                    // fp32 mode only, indexed by col
    float scale;                          // fp32 mode only
};

#define ROWB 80u          // smem bytes per row (32 halves + 8 pad)
#define MATB 10240u       // one 128-row matrix
#define BUFB 40960u       // Ah,Al,Bh,Bl per buffer
#define G_SMEM (2*40960)

__global__ __launch_bounds__(256, 1) void gemmh(const GArgs g) {
    extern __shared__ char smem[];
    uint32_t sb = s2u(smem);
    const int tid  = threadIdx.x;
    const int lane = tid & 31;
    const int wid  = tid >> 5;

    const int b  = blockIdx.z;
    const int m0 = blockIdx.y * 128;
    const int n0 = blockIdx.x * 128;
    const __half* Ah = g.Ah + (long long)b * g.sA + (long long)m0 * g.lda;
    const __half* Al = g.Al + (long long)b * g.sA + (long long)m0 * g.lda;
    const __half* Bh = g.Bh + (long long)b * g.sB + (long long)n0 * g.ldb;
    const __half* Bl = g.Bl + (long long)b * g.sB + (long long)n0 * g.ldb;

    const int NK = g.K >> 5;

    auto load_chunk = [&](int kc) {
        uint32_t base = sb + (uint32_t)(kc & 1) * BUFB;
        int ko = kc << 5;
        #pragma unroll
        for (int it = 0; it < 2; it++) {
            int u = tid + it * 256;            // 512 chunks per matrix
            int r = u >> 2, cu = u & 3;
            uint32_t off = (uint32_t)r * ROWB + (uint32_t)cu * 16u;
            cpa16(base + off,          Ah + (size_t)r * g.lda + ko + cu * 8);
            cpa16(base + MATB + off,   Al + (size_t)r * g.lda + ko + cu * 8);
            cpa16(base + 2*MATB + off, Bh + (size_t)r * g.ldb + ko + cu * 8);
            cpa16(base + 3*MATB + off, Bl + (size_t)r * g.ldb + ko + cu * 8);
        }
        cp_commit();
    };

    float acc[2][8][4];
    #pragma unroll
    for (int i = 0; i < 2; i++)
        #pragma unroll
        for (int j = 0; j < 8; j++)
            #pragma unroll
            for (int q = 0; q < 4; q++) acc[i][j][q] = 0.f;

    const int m0w = (wid >> 1) * 32;
    const int n0w = (wid & 1) * 64;
    const int l16 = lane & 15, hi = lane >> 4;

    load_chunk(0);
    for (int kc = 0; kc < NK; kc++) {
        if (kc + 1 < NK) { load_chunk(kc + 1); cp_wait1(); }
        else             { cp_wait0(); }
        __syncthreads();

        uint32_t base  = sb + (uint32_t)(kc & 1) * BUFB;
        uint32_t aAddr = base + (uint32_t)(m0w + l16) * ROWB + (uint32_t)hi * 16u;
        uint32_t bAddr = base + 2*MATB + (uint32_t)(n0w + l16) * ROWB + (uint32_t)hi * 16u;

        #pragma unroll
        for (int ks = 0; ks < 2; ks++) {
            uint32_t koff = (uint32_t)ks * 32u;
            uint32_t ah[2][4], al[2][4], bh[4][4], bl[4][4];
            ldsm4(ah[0][0], ah[0][1], ah[0][2], ah[0][3], aAddr + koff);
            ldsm4(ah[1][0], ah[1][1], ah[1][2], ah[1][3], aAddr + 16*ROWB + koff);
            ldsm4(al[0][0], al[0][1], al[0][2], al[0][3], aAddr + MATB + koff);
            ldsm4(al[1][0], al[1][1], al[1][2], al[1][3], aAddr + MATB + 16*ROWB + koff);
            #pragma unroll
            for (int nt = 0; nt < 4; nt++) {
                ldsm4(bh[nt][0], bh[nt][1], bh[nt][2], bh[nt][3], bAddr + (uint32_t)nt*16*ROWB + koff);
                ldsm4(bl[nt][0], bl[nt][1], bl[nt][2], bl[nt][3], bAddr + MATB + (uint32_t)nt*16*ROWB + koff);
            }
            #pragma unroll
            for (int mi = 0; mi < 2; mi++) {
                #pragma unroll
                for (int nj = 0; nj < 8; nj++) {
                    int nt = nj >> 1, sel = nj & 1;
                    uint32_t bh0 = sel ? bh[nt][1] : bh[nt][0];
                    uint32_t bh1 = sel ? bh[nt][3] : bh[nt][2];
                    uint32_t bl0 = sel ? bl[nt][1] : bl[nt][0];
                    uint32_t bl1 = sel ? bl[nt][3] : bl[nt][2];
                    mma16816(acc[mi][nj], ah[mi], bh0, bh1);
                    mma16816(acc[mi][nj], ah[mi], bl0, bl1);
                    mma16816(acc[mi][nj], al[mi], bh0, bh1);
                }
            }
        }
        __syncthreads();
    }

    // ---- epilogue: registers -> gmem ----
    const int rowBase = m0 + m0w + (lane >> 2);
    const int colBase = n0 + n0w + (lane & 3) * 2;
    if (g.Cf) {
        float* C = g.Cf + (long long)b * g.sC;
        #pragma unroll
        for (int mi = 0; mi < 2; mi++) {
            #pragma unroll
            for (int nj = 0; nj < 8; nj++) {
                int c = colBase + nj * 8;
                #pragma unroll
                for (int half = 0; half < 2; half++) {
                    int r = rowBase + mi * 16 + half * 8;
                    float2 v;
                    v.x = acc[mi][nj][half*2 + 0] * g.scale;
                    v.y = acc[mi][nj][half*2 + 1] * g.scale;
                    if (g.bias) { v.x += g.bias[c]; v.y += g.bias[c + 1]; }
                    *(float2*)(C + (long long)r * g.ldc + c) = v;
                }
            }
        }
    } else {
        __half* Ch = g.Ch + (long long)b * g.sC;
        __half* Cl = g.Cl + (long long)b * g.sC;
        #pragma unroll
        for (int mi = 0; mi < 2; mi++) {
            #pragma unroll
            for (int nj = 0; nj < 8; nj++) {
                int c = colBase + nj * 8;
                #pragma unroll
                for (int half = 0; half < 2; half++) {
                    int r = rowBase + mi * 16 + half * 8;
                    float v0 = acc[mi][nj][half*2 + 0];
                    float v1 = acc[mi][nj][half*2 + 1];
                    __half h0 = __float2half_rn(v0), h1 = __float2half_rn(v1);
                    __half l0 = __float2half_rn(v0 - __half2float(h0));
                    __half l1 = __float2half_rn(v1 - __half2float(h1));
                    *(__half2*)(Ch + (long long)r * g.ldc + c) = __halves2half2(h0, h1);
                    *(__half2*)(Cl + (long long)r * g.ldc + c) = __halves2half2(l0, l1);
                }
            }
        }
    }
}

// ---------------- w3 transpose ----------------
__global__ __launch_bounds__(256) void w3t_kernel(const float* __restrict__ w3q,
                                                  const float* __restrict__ w3k,
                                                  const float* __restrict__ w3v) {
    int oi = blockIdx.x * 256 + threadIdx.x;
    int br = blockIdx.y;
    const float* w3 = br == 0 ? w3q : br == 1 ? w3k : w3v;
    float a = w3[(size_t)oi*3 + 0];
    float b = w3[(size_t)oi*3 + 1];
    float c = w3[(size_t)oi*3 + 2];
    g_w3t[(size_t)(br*3 + 0)*262144 + oi] = a;
    g_w3t[(size_t)(br*3 + 1)*262144 + oi] = b;
    g_w3t[(size_t)(br*3 + 2)*262144 + oi] = c;
}

// ---------------- weff (fp32 SIMT; tiny) ----------------
__global__ __launch_bounds__(256) void weff2(const float* __restrict__ w1q,
                                             const float* __restrict__ w1k,
                                             const float* __restrict__ w1v) {
    int z = blockIdx.z;
    int br = z / 3, t = z - br*3;
    const float* A  = g_w3t + (size_t)z * 262144;
    const float* w1 = br == 0 ? w1q : br == 1 ? w1k : w1v;
    int n0 = blockIdx.x * 64, m0 = blockIdx.y * 64;
    __shared__ float As[64][17];
    __shared__ float Bs[16][64];
    int tid = threadIdx.x;
    int tx = tid & 15, ty = tid >> 4;
    float acc[4][4] = {};
    for (int k0 = 0; k0 < 512; k0 += 16) {
        {
            int kk = tid & 15, mmb = tid >> 4;
            #pragma unroll
            for (int j = 0; j < 4; j++) {
                int mm = mmb + j*16;
                As[mm][kk] = A[(size_t)(m0+mm)*512 + k0 + kk];
            }
        }
        {
            int nn = tid & 63, kkb = tid >> 6;
            #pragma unroll
            for (int j = 0; j < 4; j++) {
                int kk = kkb + j*4;
                Bs[kk][nn] = w1[(size_t)(k0+kk)*512 + n0 + nn];
            }
        }
        __syncthreads();
        #pragma unroll
        for (int kk = 0; kk < 16; kk++) {
            float a[4];
            #pragma unroll
            for (int i = 0; i < 4; i++) a[i] = As[ty*4+i][kk];
            float4 bv = *(const float4*)&Bs[kk][tx*4];
            float bf[4] = {bv.x, bv.y, bv.z, bv.w};
            #pragma unroll
            for (int i = 0; i < 4; i++)
                #pragma unroll
                for (int j = 0; j < 4; j++) acc[i][j] += a[i]*bf[j];
        }
        __syncthreads();
    }
    #pragma unroll
    for (int i = 0; i < 4; i++) {
        int o = m0 + ty*4 + i;
        #pragma unroll
        for (int j = 0; j < 4; j++) {
            int c = n0 + tx*4 + j;
            g_weff[(size_t)(br*512 + o)*K3 + t*512 + c] = acc[i][j];
        }
    }
}

// ---------------- splits ----------------
__global__ __launch_bounds__(256) void split_weff() {
    size_t i = (size_t)blockIdx.x * 256 + threadIdx.x;
    float v = g_weff[i];
    __half h = __float2half_rn(v);
    g_wh[i] = h; g_wl[i] = __float2half_rn(v - __half2float(h));
}
__global__ __launch_bounds__(256) void split_wproj(const float* __restrict__ w) {
    size_t i = (size_t)blockIdx.x * 256 + threadIdx.x;
    float v = w[i];
    __half h = __float2half_rn(v);
    g_wph[i] = h; g_wpl[i] = __float2half_rn(v - __half2float(h));
}

// ---------------- Xmat build ----------------
__global__ __launch_bounds__(256) void build_xmat(const float* __restrict__ x) {
    int b = blockIdx.y, n = blockIdx.x;
    size_t dst = ((size_t)b * Nn + n) * K3;
    #pragma unroll
    for (int t = 0; t < 3; t++) {
        int ns = n + t - 1;
        if (ns < 0) ns += Nn; else if (ns >= Nn) ns -= Nn;
        const float* row = x + ((size_t)b * Nn + ns) * Cc;
        for (int c = threadIdx.x; c < Cc; c += 256) {
            float v = row[c];
            __half h = __float2half_rn(v);
            g_xh[dst + t*Cc + c] = h;
            g_xl[dst + t*Cc + c] = __float2half_rn(v - __half2float(h));
        }
    }
}

// ---------------- v transpose ----------------
__global__ __launch_bounds__(256) void vtrans() {
    __shared__ __half t0[32][33];
    __shared__ __half t1[32][33];
    int b = blockIdx.z;
    int n0 = blockIdx.x * 32, d0 = blockIdx.y * 32;
    int tx = threadIdx.x, ty = threadIdx.y;
    const __half* sh = g_qkvh + (size_t)b*K3*Nn + (size_t)(1024 + d0)*Nn + n0;
    const __half* sl = g_qkvl + (size_t)b*K3*Nn + (size_t)(1024 + d0)*Nn + n0;
    #pragma unroll
    for (int i = 0; i < 32; i += 8) {
        t0[ty+i][tx] = sh[(size_t)(ty+i)*Nn + tx];
        t1[ty+i][tx] = sl[(size_t)(ty+i)*Nn + tx];
    }
    __syncthreads();
    __half* dh = g_vth + (size_t)b*Nn*Cc;
    __half* dl = g_vtl + (size_t)b*Nn*Cc;
    #pragma unroll
    for (int i = 0; i < 32; i += 8) {
        dh[(size_t)(n0+ty+i)*Cc + d0 + tx] = t0[tx][ty+i];
        dl[(size_t)(n0+ty+i)*Cc + d0 + tx] = t1[tx][ty+i];
    }
}

// ---------------- softmax -> split P ----------------
__global__ __launch_bounds__(256) void softmax_split() {
    size_t row = blockIdx.x;
    const float* p = g_S + row * Cc;
    int tid = threadIdx.x;
    float v0 = p[tid], v1 = p[tid + 256];
    float m = fmaxf(v0, v1);
    __shared__ float red[8];
    #pragma unroll
    for (int o = 16; o > 0; o >>= 1) m = fmaxf(m, __shfl_xor_sync(0xffffffffu, m, o));
    if ((tid & 31) == 0) red[tid >> 5] = m;
    __syncthreads();
    float mm = red[0];
    #pragma unroll
    for (int i = 1; i < 8; i++) mm = fmaxf(mm, red[i]);
    float e0 = __expf(v0 - mm), e1 = __expf(v1 - mm);
    float s = e0 + e1;
    #pragma unroll
    for (int o = 16; o > 0; o >>= 1) s += __shfl_xor_sync(0xffffffffu, s, o);
    __syncthreads();
    if ((tid & 31) == 0) red[tid >> 5] = s;
    __syncthreads();
    float ss = 0.f;
    #pragma unroll
    for (int i = 0; i < 8; i++) ss += red[i];
    float inv = 1.0f / ss;
    float q0 = e0 * inv, q1 = e1 * inv;
    __half h0 = __float2half_rn(q0), h1 = __float2half_rn(q1);
    g_ph[row*Cc + tid]       = h0;
    g_pl[row*Cc + tid]       = __float2half_rn(q0 - __half2float(h0));
    g_ph[row*Cc + tid + 256] = h1;
    g_pl[row*Cc + tid + 256] = __float2half_rn(q1 - __half2float(h1));
}

// ---------------- launch ----------------
static void* sym(const void* s) { void* p = nullptr; cudaGetSymbolAddress(&p, s); return p; }

extern "C" void kernel_launch(void* const* d_in, const int* in_sizes, int n_in,
                              void* d_out, int out_size) {
    const float* x     = (const float*)d_in[0];
    const float* w1q   = (const float*)d_in[1];
    const float* w3q   = (const float*)d_in[2];
    const float* w1k   = (const float*)d_in[3];
    const float* w3k   = (const float*)d_in[4];
    const float* w1v   = (const float*)d_in[5];
    const float* w3v   = (const float*)d_in[6];
    const float* wproj = (const float*)d_in[7];
    const float* bproj = (const float*)d_in[8];
    float* y = (float*)d_out;

    cudaFuncSetAttribute(gemmh, cudaFuncAttributeMaxDynamicSharedMemorySize, G_SMEM);

    __half* wh   = (__half*)sym(g_wh);     __half* wl   = (__half*)sym(g_wl);
    __half* wph  = (__half*)sym(g_wph);    __half* wpl  = (__half*)sym(g_wpl);
    __half* xh   = (__half*)sym(g_xh);     __half* xl   = (__half*)sym(g_xl);
    __half* qkvh = (__half*)sym(g_qkvh);   __half* qkvl = (__half*)sym(g_qkvl);
    __half* vth  = (__half*)sym(g_vth);    __half* vtl  = (__half*)sym(g_vtl);
    float*  Sf   = (float*) sym(g_S);
    __half* phh  = (__half*)sym(g_ph);     __half* pll  = (__half*)sym(g_pl);
    __half* oth  = (__half*)sym(g_oth);    __half* otl  = (__half*)sym(g_otl);

    // weights prep
    w3t_kernel<<<dim3(1024, 3), 256>>>(w3q, w3k, w3v);
    weff2<<<dim3(8, 8, 9), 256>>>(w1q, w1k, w1v);
    split_weff<<<9216, 256>>>();
    split_wproj<<<1024, 256>>>(wproj);
    build_xmat<<<dim3(Nn, Bb), 256>>>(x);

    // QKV: [3C x N] = Weff[3C x K3] * Xmat[N x K3]^T
    {
        GArgs a = {};
        a.Ah = wh; a.Al = wl; a.Bh = xh; a.Bl = xl;
        a.sA = 0; a.sB = (long long)Nn * K3; a.sC = (long long)K3 * Nn;
        a.lda = K3; a.ldb = K3; a.ldc = Nn; a.K = K3;
        a.Cf = nullptr; a.Ch = qkvh; a.Cl = qkvl; a.bias = nullptr; a.scale = 1.f;
        gemmh<<<dim3(Nn/128, K3/128, Bb), 256, G_SMEM>>>(a);
    }
    vtrans<<<dim3(Nn/32, Cc/32, Bb), dim3(32, 8)>>>();

    // scores: S[c,d] = (1/C) * q . k
    {
        GArgs a = {};
        a.Ah = qkvh; a.Al = qkvl;
        a.Bh = qkvh + (size_t)512*Nn; a.Bl = qkvl + (size_t)512*Nn;
        a.sA = (long long)K3 * Nn; a.sB = (long long)K3 * Nn; a.sC = (long long)Cc * Cc;
        a.lda = Nn; a.ldb = Nn; a.ldc = Cc; a.K = Nn;
        a.Cf = Sf; a.Ch = nullptr; a.Cl = nullptr; a.bias = nullptr; a.scale = 1.0f / (float)Cc;
        gemmh<<<dim3(Cc/128, Cc/128, Bb), 256, G_SMEM>>>(a);
    }
    softmax_split<<<Bb*Cc, 256>>>();

    // PV: Ot[n,c] = sum_d vt[n,d] * P[c,d]
    {
        GArgs a = {};
        a.Ah = vth; a.Al = vtl; a.Bh = phh; a.Bl = pll;
        a.sA = (long long)Nn * Cc; a.sB = (long long)Cc * Cc; a.sC = (long long)Nn * Cc;
        a.lda = Cc; a.ldb = Cc; a.ldc = Cc; a.K = Cc;
        a.Cf = nullptr; a.Ch = oth; a.Cl = otl; a.bias = nullptr; a.scale = 1.f;
        gemmh<<<dim3(Cc/128, Nn/128, Bb), 256, G_SMEM>>>(a);
    }

    // proj: y[n,o] = sum_c Ot[n,c] * wproj[o,c] + bias[o]
    {
        GArgs a = {};
        a.Ah = oth; a.Al = otl; a.Bh = wph; a.Bl = wpl;
        a.sA = (long long)Nn * Cc; a.sB = 0; a.sC = (long long)Nn * Cc;
        a.lda = Cc; a.ldb = Cc; a.ldc = Cc; a.K = Cc;
        a.Cf = y; a.Ch = nullptr; a.Cl = nullptr; a.bias = bproj; a.scale = 1.f;
        gemmh<<<dim3(Cc/128, Nn/128, Bb), 256, G_SMEM>>>(a);
    }
}

// round 4
// speedup vs baseline: 3.4286x; 1.3341x over previous
#include <cuda_runtime.h>
#include <cuda_fp16.h>
#include <cstdint>

#define Bb 16
#define Nn 2048
#define Cc 512
#define K3 1536

// ---------------- device scratch (no allocations) ----------------
__device__ float  g_w3t [9*512*512];          // [br*3+t][o][i]
__device__ float  g_weff[1536*1536];          // [br*512+o][t*512+c]
__device__ __half g_wh [1536*1536];
__device__ __half g_wl [1536*1536];
__device__ __half g_wph[512*512];
__device__ __half g_wpl[512*512];
__device__ __half g_xh [50331648];            // [b][n][t*512+c]
__device__ __half g_qkvh[50331648];           // [b][3C][N]
__device__ __half g_qkvl[50331648];
__device__ __half g_vth[16777216];            // [b][n][d]
__device__ __half g_vtl[16777216];
__device__ float  g_S  [4194304];             // [b][c][d]
__device__ __half g_ph [4194304];
__device__ __half g_pl [4194304];
__device__ __half g_oth[16777216];            // [b][n][c]
__device__ __half g_otl[16777216];

// ---------------- PTX helpers ----------------
__device__ __forceinline__ uint32_t s2u(const void* p){
    uint32_t a; asm("{ .reg .u64 t; cvta.to.shared.u64 t, %1; cvt.u32.u64 %0, t; }" : "=r"(a) : "l"(p)); return a;
}
__device__ __forceinline__ void cpa16(uint32_t d, const void* s){
    asm volatile("cp.async.cg.shared.global [%0], [%1], 16;" :: "r"(d), "l"(s));
}
__device__ __forceinline__ void cp_commit(){ asm volatile("cp.async.commit_group;"); }
__device__ __forceinline__ void cp_wait1(){ asm volatile("cp.async.wait_group 1;"); }
__device__ __forceinline__ void cp_wait0(){ asm volatile("cp.async.wait_group 0;"); }
__device__ __forceinline__ void ldsm4(uint32_t& r0, uint32_t& r1, uint32_t& r2, uint32_t& r3, uint32_t a){
    asm volatile("ldmatrix.sync.aligned.m8n8.x4.shared.b16 {%0,%1,%2,%3}, [%4];"
        : "=r"(r0), "=r"(r1), "=r"(r2), "=r"(r3) : "r"(a));
}
__device__ __forceinline__ void mma16816(float* d, const uint32_t* a, uint32_t b0, uint32_t b1){
    asm volatile("mma.sync.aligned.m16n8k16.row.col.f32.f16.f16.f32 "
        "{%0,%1,%2,%3}, {%4,%5,%6,%7}, {%8,%9}, {%0,%1,%2,%3};"
        : "+f"(d[0]), "+f"(d[1]), "+f"(d[2]), "+f"(d[3])
        : "r"(a[0]), "r"(a[1]), "r"(a[2]), "r"(a[3]), "r"(b0), "r"(b1));
}

#define ROWB 80u          // smem bytes per row (32 halves + 8 pad)
#define MATB 10240u       // one 128-row matrix

// =====================================================================
// gemm2h: D = (Ah+Al) * B^T, split-half output. 2 MMA passes per tile.
// CTA 128x128, warps 4Mx2N, K-stage 32, double buffer, 2 CTAs/SM.
// =====================================================================
struct G2Args {
    const __half* Ah; const __half* Al; const __half* B;
    long long sA, sB, sC;
    int lda, ldb, ldc, K;
    __half* Ch; __half* Cl;
};

#define BUF2 30720u
#define G2_SMEM (2*30720)

__global__ __launch_bounds__(256, 2) void gemm2h(const G2Args g) {
    extern __shared__ char smem[];
    uint32_t sb = s2u(smem);
    const int tid  = threadIdx.x;
    const int lane = tid & 31;
    const int wid  = tid >> 5;

    const int b  = blockIdx.z;
    const int m0 = blockIdx.y * 128;
    const int n0 = blockIdx.x * 128;
    const __half* Ah = g.Ah + (long long)b * g.sA + (long long)m0 * g.lda;
    const __half* Al = g.Al + (long long)b * g.sA + (long long)m0 * g.lda;
    const __half* Bp = g.B  + (long long)b * g.sB + (long long)n0 * g.ldb;

    const int NK = g.K >> 5;

    auto load_chunk = [&](int kc) {
        uint32_t base = sb + (uint32_t)(kc & 1) * BUF2;
        int ko = kc << 5;
        #pragma unroll
        for (int it = 0; it < 2; it++) {
            int u = tid + it * 256;
            int r = u >> 2, cu = u & 3;
            uint32_t off = (uint32_t)r * ROWB + (uint32_t)cu * 16u;
            cpa16(base + off,          Ah + (size_t)r * g.lda + ko + cu * 8);
            cpa16(base + MATB + off,   Al + (size_t)r * g.lda + ko + cu * 8);
            cpa16(base + 2*MATB + off, Bp + (size_t)r * g.ldb + ko + cu * 8);
        }
        cp_commit();
    };

    float acc[2][8][4];
    #pragma unroll
    for (int i = 0; i < 2; i++)
        #pragma unroll
        for (int j = 0; j < 8; j++)
            #pragma unroll
            for (int q = 0; q < 4; q++) acc[i][j][q] = 0.f;

    const int m0w = (wid >> 1) * 32;
    const int n0w = (wid & 1) * 64;
    const int l16 = lane & 15, hi = lane >> 4;

    load_chunk(0);
    for (int kc = 0; kc < NK; kc++) {
        if (kc + 1 < NK) { load_chunk(kc + 1); cp_wait1(); }
        else             { cp_wait0(); }
        __syncthreads();

        uint32_t base  = sb + (uint32_t)(kc & 1) * BUF2;
        uint32_t aAddr = base + (uint32_t)(m0w + l16) * ROWB + (uint32_t)hi * 16u;
        uint32_t bAddr = base + 2*MATB + (uint32_t)(n0w + l16) * ROWB + (uint32_t)hi * 16u;

        #pragma unroll
        for (int ks = 0; ks < 2; ks++) {
            uint32_t koff = (uint32_t)ks * 32u;
            uint32_t ah[2][4], al[2][4], bv[4][4];
            ldsm4(ah[0][0], ah[0][1], ah[0][2], ah[0][3], aAddr + koff);
            ldsm4(ah[1][0], ah[1][1], ah[1][2], ah[1][3], aAddr + 16*ROWB + koff);
            ldsm4(al[0][0], al[0][1], al[0][2], al[0][3], aAddr + MATB + koff);
            ldsm4(al[1][0], al[1][1], al[1][2], al[1][3], aAddr + MATB + 16*ROWB + koff);
            #pragma unroll
            for (int nt = 0; nt < 4; nt++)
                ldsm4(bv[nt][0], bv[nt][1], bv[nt][2], bv[nt][3], bAddr + (uint32_t)nt*16*ROWB + koff);
            #pragma unroll
            for (int mi = 0; mi < 2; mi++) {
                #pragma unroll
                for (int nj = 0; nj < 8; nj++) {
                    int nt = nj >> 1, sel = nj & 1;
                    uint32_t b0 = sel ? bv[nt][1] : bv[nt][0];
                    uint32_t b1 = sel ? bv[nt][3] : bv[nt][2];
                    mma16816(acc[mi][nj], ah[mi], b0, b1);
                    mma16816(acc[mi][nj], al[mi], b0, b1);
                }
            }
        }
        __syncthreads();
    }

    const int rowBase = m0 + m0w + (lane >> 2);
    const int colBase = n0 + n0w + (lane & 3) * 2;
    __half* Ch = g.Ch + (long long)b * g.sC;
    __half* Cl = g.Cl + (long long)b * g.sC;
    #pragma unroll
    for (int mi = 0; mi < 2; mi++) {
        #pragma unroll
        for (int nj = 0; nj < 8; nj++) {
            int c = colBase + nj * 8;
            #pragma unroll
            for (int half = 0; half < 2; half++) {
                int r = rowBase + mi * 16 + half * 8;
                float v0 = acc[mi][nj][half*2 + 0];
                float v1 = acc[mi][nj][half*2 + 1];
                __half h0 = __float2half_rn(v0), h1 = __float2half_rn(v1);
                __half l0 = __float2half_rn(v0 - __half2float(h0));
                __half l1 = __float2half_rn(v1 - __half2float(h1));
                *(__half2*)(Ch + (long long)r * g.ldc + c) = __halves2half2(h0, h1);
                *(__half2*)(Cl + (long long)r * g.ldc + c) = __halves2half2(l0, l1);
            }
        }
    }
}

// =====================================================================
// gemmh: x3-split GEMM (unchanged from round 3) for scores / PV / proj
// =====================================================================
struct GArgs {
    const __half* Ah; const __half* Al;
    const __half* Bh; const __half* Bl;
    long long sA, sB, sC;
    int lda, ldb, ldc, K;
    float* Cf; __half* Ch; __half* Cl;
    const float* bias;
    float scale;
};

#define BUFB 40960u
#define G_SMEM (2*40960)

__global__ __launch_bounds__(256, 1) void gemmh(const GArgs g) {
    extern __shared__ char smem[];
    uint32_t sb = s2u(smem);
    const int tid  = threadIdx.x;
    const int lane = tid & 31;
    const int wid  = tid >> 5;

    const int b  = blockIdx.z;
    const int m0 = blockIdx.y * 128;
    const int n0 = blockIdx.x * 128;
    const __half* Ah = g.Ah + (long long)b * g.sA + (long long)m0 * g.lda;
    const __half* Al = g.Al + (long long)b * g.sA + (long long)m0 * g.lda;
    const __half* Bh = g.Bh + (long long)b * g.sB + (long long)n0 * g.ldb;
    const __half* Bl = g.Bl + (long long)b * g.sB + (long long)n0 * g.ldb;

    const int NK = g.K >> 5;

    auto load_chunk = [&](int kc) {
        uint32_t base = sb + (uint32_t)(kc & 1) * BUFB;
        int ko = kc << 5;
        #pragma unroll
        for (int it = 0; it < 2; it++) {
            int u = tid + it * 256;
            int r = u >> 2, cu = u & 3;
            uint32_t off = (uint32_t)r * ROWB + (uint32_t)cu * 16u;
            cpa16(base + off,          Ah + (size_t)r * g.lda + ko + cu * 8);
            cpa16(base + MATB + off,   Al + (size_t)r * g.lda + ko + cu * 8);
            cpa16(base + 2*MATB + off, Bh + (size_t)r * g.ldb + ko + cu * 8);
            cpa16(base + 3*MATB + off, Bl + (size_t)r * g.ldb + ko + cu * 8);
        }
        cp_commit();
    };

    float acc[2][8][4];
    #pragma unroll
    for (int i = 0; i < 2; i++)
        #pragma unroll
        for (int j = 0; j < 8; j++)
            #pragma unroll
            for (int q = 0; q < 4; q++) acc[i][j][q] = 0.f;

    const int m0w = (wid >> 1) * 32;
    const int n0w = (wid & 1) * 64;
    const int l16 = lane & 15, hi = lane >> 4;

    load_chunk(0);
    for (int kc = 0; kc < NK; kc++) {
        if (kc + 1 < NK) { load_chunk(kc + 1); cp_wait1(); }
        else             { cp_wait0(); }
        __syncthreads();

        uint32_t base  = sb + (uint32_t)(kc & 1) * BUFB;
        uint32_t aAddr = base + (uint32_t)(m0w + l16) * ROWB + (uint32_t)hi * 16u;
        uint32_t bAddr = base + 2*MATB + (uint32_t)(n0w + l16) * ROWB + (uint32_t)hi * 16u;

        #pragma unroll
        for (int ks = 0; ks < 2; ks++) {
            uint32_t koff = (uint32_t)ks * 32u;
            uint32_t ah[2][4], al[2][4], bh[4][4], bl[4][4];
            ldsm4(ah[0][0], ah[0][1], ah[0][2], ah[0][3], aAddr + koff);
            ldsm4(ah[1][0], ah[1][1], ah[1][2], ah[1][3], aAddr + 16*ROWB + koff);
            ldsm4(al[0][0], al[0][1], al[0][2], al[0][3], aAddr + MATB + koff);
            ldsm4(al[1][0], al[1][1], al[1][2], al[1][3], aAddr + MATB + 16*ROWB + koff);
            #pragma unroll
            for (int nt = 0; nt < 4; nt++) {
                ldsm4(bh[nt][0], bh[nt][1], bh[nt][2], bh[nt][3], bAddr + (uint32_t)nt*16*ROWB + koff);
                ldsm4(bl[nt][0], bl[nt][1], bl[nt][2], bl[nt][3], bAddr + MATB + (uint32_t)nt*16*ROWB + koff);
            }
            #pragma unroll
            for (int mi = 0; mi < 2; mi++) {
                #pragma unroll
                for (int nj = 0; nj < 8; nj++) {
                    int nt = nj >> 1, sel = nj & 1;
                    uint32_t bh0 = sel ? bh[nt][1] : bh[nt][0];
                    uint32_t bh1 = sel ? bh[nt][3] : bh[nt][2];
                    uint32_t bl0 = sel ? bl[nt][1] : bl[nt][0];
                    uint32_t bl1 = sel ? bl[nt][3] : bl[nt][2];
                    mma16816(acc[mi][nj], ah[mi], bh0, bh1);
                    mma16816(acc[mi][nj], ah[mi], bl0, bl1);
                    mma16816(acc[mi][nj], al[mi], bh0, bh1);
                }
            }
        }
        __syncthreads();
    }

    const int rowBase = m0 + m0w + (lane >> 2);
    const int colBase = n0 + n0w + (lane & 3) * 2;
    if (g.Cf) {
        float* C = g.Cf + (long long)b * g.sC;
        #pragma unroll
        for (int mi = 0; mi < 2; mi++) {
            #pragma unroll
            for (int nj = 0; nj < 8; nj++) {
                int c = colBase + nj * 8;
                #pragma unroll
                for (int half = 0; half < 2; half++) {
                    int r = rowBase + mi * 16 + half * 8;
                    float2 v;
                    v.x = acc[mi][nj][half*2 + 0] * g.scale;
                    v.y = acc[mi][nj][half*2 + 1] * g.scale;
                    if (g.bias) { v.x += g.bias[c]; v.y += g.bias[c + 1]; }
                    *(float2*)(C + (long long)r * g.ldc + c) = v;
                }
            }
        }
    } else {
        __half* Ch = g.Ch + (long long)b * g.sC;
        __half* Cl = g.Cl + (long long)b * g.sC;
        #pragma unroll
        for (int mi = 0; mi < 2; mi++) {
            #pragma unroll
            for (int nj = 0; nj < 8; nj++) {
                int c = colBase + nj * 8;
                #pragma unroll
                for (int half = 0; half < 2; half++) {
                    int r = rowBase + mi * 16 + half * 8;
                    float v0 = acc[mi][nj][half*2 + 0];
                    float v1 = acc[mi][nj][half*2 + 1];
                    __half h0 = __float2half_rn(v0), h1 = __float2half_rn(v1);
                    __half l0 = __float2half_rn(v0 - __half2float(h0));
                    __half l1 = __float2half_rn(v1 - __half2float(h1));
                    *(__half2*)(Ch + (long long)r * g.ldc + c) = __halves2half2(h0, h1);
                    *(__half2*)(Cl + (long long)r * g.ldc + c) = __halves2half2(l0, l1);
                }
            }
        }
    }
}

// ---------------- w3 transpose ----------------
__global__ __launch_bounds__(256) void w3t_kernel(const float* __restrict__ w3q,
                                                  const float* __restrict__ w3k,
                                                  const float* __restrict__ w3v) {
    int oi = blockIdx.x * 256 + threadIdx.x;
    int br = blockIdx.y;
    const float* w3 = br == 0 ? w3q : br == 1 ? w3k : w3v;
    float a = w3[(size_t)oi*3 + 0];
    float b = w3[(size_t)oi*3 + 1];
    float c = w3[(size_t)oi*3 + 2];
    g_w3t[(size_t)(br*3 + 0)*262144 + oi] = a;
    g_w3t[(size_t)(br*3 + 1)*262144 + oi] = b;
    g_w3t[(size_t)(br*3 + 2)*262144 + oi] = c;
}

// ---------------- weff (fp32 SIMT; tiny) ----------------
__global__ __launch_bounds__(256) void weff2(const float* __restrict__ w1q,
                                             const float* __restrict__ w1k,
                                             const float* __restrict__ w1v) {
    int z = blockIdx.z;
    int br = z / 3, t = z - br*3;
    const float* A  = g_w3t + (size_t)z * 262144;
    const float* w1 = br == 0 ? w1q : br == 1 ? w1k : w1v;
    int n0 = blockIdx.x * 64, m0 = blockIdx.y * 64;
    __shared__ float As[64][17];
    __shared__ float Bs[16][64];
    int tid = threadIdx.x;
    int tx = tid & 15, ty = tid >> 4;
    float acc[4][4] = {};
    for (int k0 = 0; k0 < 512; k0 += 16) {
        {
            int kk = tid & 15, mmb = tid >> 4;
            #pragma unroll
            for (int j = 0; j < 4; j++) {
                int mm = mmb + j*16;
                As[mm][kk] = A[(size_t)(m0+mm)*512 + k0 + kk];
            }
        }
        {
            int nn = tid & 63, kkb = tid >> 6;
            #pragma unroll
            for (int j = 0; j < 4; j++) {
                int kk = kkb + j*4;
                Bs[kk][nn] = w1[(size_t)(k0+kk)*512 + n0 + nn];
            }
        }
        __syncthreads();
        #pragma unroll
        for (int kk = 0; kk < 16; kk++) {
            float a[4];
            #pragma unroll
            for (int i = 0; i < 4; i++) a[i] = As[ty*4+i][kk];
            float4 bv = *(const float4*)&Bs[kk][tx*4];
            float bf[4] = {bv.x, bv.y, bv.z, bv.w};
            #pragma unroll
            for (int i = 0; i < 4; i++)
                #pragma unroll
                for (int j = 0; j < 4; j++) acc[i][j] += a[i]*bf[j];
        }
        __syncthreads();
    }
    #pragma unroll
    for (int i = 0; i < 4; i++) {
        int o = m0 + ty*4 + i;
        #pragma unroll
        for (int j = 0; j < 4; j++) {
            int c = n0 + tx*4 + j;
            g_weff[(size_t)(br*512 + o)*K3 + t*512 + c] = acc[i][j];
        }
    }
}

// ---------------- splits ----------------
__global__ __launch_bounds__(256) void split_weff() {
    size_t i = (size_t)blockIdx.x * 256 + threadIdx.x;
    float v = g_weff[i];
    __half h = __float2half_rn(v);
    g_wh[i] = h; g_wl[i] = __float2half_rn(v - __half2float(h));
}
__global__ __launch_bounds__(256) void split_wproj(const float* __restrict__ w) {
    size_t i = (size_t)blockIdx.x * 256 + threadIdx.x;
    float v = w[i];
    __half h = __float2half_rn(v);
    g_wph[i] = h; g_wpl[i] = __float2half_rn(v - __half2float(h));
}

// ---------------- Xmat build (hi part only) ----------------
__global__ __launch_bounds__(256) void build_xmat(const float* __restrict__ x) {
    int b = blockIdx.y, n = blockIdx.x;
    size_t dst = ((size_t)b * Nn + n) * K3;
    #pragma unroll
    for (int t = 0; t < 3; t++) {
        int ns = n + t - 1;
        if (ns < 0) ns += Nn; else if (ns >= Nn) ns -= Nn;
        const float* row = x + ((size_t)b * Nn + ns) * Cc;
        for (int c = threadIdx.x; c < Cc; c += 256)
            g_xh[dst + t*Cc + c] = __float2half_rn(row[c]);
    }
}

// ---------------- v transpose ----------------
__global__ __launch_bounds__(256) void vtrans() {
    __shared__ __half t0[32][33];
    __shared__ __half t1[32][33];
    int b = blockIdx.z;
    int n0 = blockIdx.x * 32, d0 = blockIdx.y * 32;
    int tx = threadIdx.x, ty = threadIdx.y;
    const __half* sh = g_qkvh + (size_t)b*K3*Nn + (size_t)(1024 + d0)*Nn + n0;
    const __half* sl = g_qkvl + (size_t)b*K3*Nn + (size_t)(1024 + d0)*Nn + n0;
    #pragma unroll
    for (int i = 0; i < 32; i += 8) {
        t0[ty+i][tx] = sh[(size_t)(ty+i)*Nn + tx];
        t1[ty+i][tx] = sl[(size_t)(ty+i)*Nn + tx];
    }
    __syncthreads();
    __half* dh = g_vth + (size_t)b*Nn*Cc;
    __half* dl = g_vtl + (size_t)b*Nn*Cc;
    #pragma unroll
    for (int i = 0; i < 32; i += 8) {
        dh[(size_t)(n0+ty+i)*Cc + d0 + tx] = t0[tx][ty+i];
        dl[(size_t)(n0+ty+i)*Cc + d0 + tx] = t1[tx][ty+i];
    }
}

// ---------------- softmax -> split P ----------------
__global__ __launch_bounds__(256) void softmax_split() {
    size_t row = blockIdx.x;
    const float* p = g_S + row * Cc;
    int tid = threadIdx.x;
    float v0 = p[tid], v1 = p[tid + 256];
    float m = fmaxf(v0, v1);
    __shared__ float red[8];
    #pragma unroll
    for (int o = 16; o > 0; o >>= 1) m = fmaxf(m, __shfl_xor_sync(0xffffffffu, m, o));
    if ((tid & 31) == 0) red[tid >> 5] = m;
    __syncthreads();
    float mm = red[0];
    #pragma unroll
    for (int i = 1; i < 8; i++) mm = fmaxf(mm, red[i]);
    float e0 = __expf(v0 - mm), e1 = __expf(v1 - mm);
    float s = e0 + e1;
    #pragma unroll
    for (int o = 16; o > 0; o >>= 1) s += __shfl_xor_sync(0xffffffffu, s, o);
    __syncthreads();
    if ((tid & 31) == 0) red[tid >> 5] = s;
    __syncthreads();
    float ss = 0.f;
    #pragma unroll
    for (int i = 0; i < 8; i++) ss += red[i];
    float inv = 1.0f / ss;
    float q0 = e0 * inv, q1 = e1 * inv;
    __half h0 = __float2half_rn(q0), h1 = __float2half_rn(q1);
    g_ph[row*Cc + tid]       = h0;
    g_pl[row*Cc + tid]       = __float2half_rn(q0 - __half2float(h0));
    g_ph[row*Cc + tid + 256] = h1;
    g_pl[row*Cc + tid + 256] = __float2half_rn(q1 - __half2float(h1));
}

// ---------------- launch ----------------
static void* sym(const void* s) { void* p = nullptr; cudaGetSymbolAddress(&p, s); return p; }

extern "C" void kernel_launch(void* const* d_in, const int* in_sizes, int n_in,
                              void* d_out, int out_size) {
    const float* x     = (const float*)d_in[0];
    const float* w1q   = (const float*)d_in[1];
    const float* w3q   = (const float*)d_in[2];
    const float* w1k   = (const float*)d_in[3];
    const float* w3k   = (const float*)d_in[4];
    const float* w1v   = (const float*)d_in[5];
    const float* w3v   = (const float*)d_in[6];
    const float* wproj = (const float*)d_in[7];
    const float* bproj = (const float*)d_in[8];
    float* y = (float*)d_out;

    cudaFuncSetAttribute(gemmh,  cudaFuncAttributeMaxDynamicSharedMemorySize, G_SMEM);
    cudaFuncSetAttribute(gemm2h, cudaFuncAttributeMaxDynamicSharedMemorySize, G2_SMEM);

    __half* wh   = (__half*)sym(g_wh);     __half* wl   = (__half*)sym(g_wl);
    __half* wph  = (__half*)sym(g_wph);    __half* wpl  = (__half*)sym(g_wpl);
    __half* xh   = (__half*)sym(g_xh);
    __half* qkvh = (__half*)sym(g_qkvh);   __half* qkvl = (__half*)sym(g_qkvl);
    __half* vth  = (__half*)sym(g_vth);    __half* vtl  = (__half*)sym(g_vtl);
    float*  Sf   = (float*) sym(g_S);
    __half* phh  = (__half*)sym(g_ph);     __half* pll  = (__half*)sym(g_pl);
    __half* oth  = (__half*)sym(g_oth);    __half* otl  = (__half*)sym(g_otl);

    // weights prep
    w3t_kernel<<<dim3(1024, 3), 256>>>(w3q, w3k, w3v);
    weff2<<<dim3(8, 8, 9), 256>>>(w1q, w1k, w1v);
    split_weff<<<9216, 256>>>();
    split_wproj<<<1024, 256>>>(wproj);
    build_xmat<<<dim3(Nn, Bb), 256>>>(x);

    // QKV (2-pass, weights split, x plain fp16): [3C x N] = Weff * Xmat^T
    {
        G2Args a = {};
        a.Ah = wh; a.Al = wl; a.B = xh;
        a.sA = 0; a.sB = (long long)Nn * K3; a.sC = (long long)K3 * Nn;
        a.lda = K3; a.ldb = K3; a.ldc = Nn; a.K = K3;
        a.Ch = qkvh; a.Cl = qkvl;
        gemm2h<<<dim3(Nn/128, K3/128, Bb), 256, G2_SMEM>>>(a);
    }
    vtrans<<<dim3(Nn/32, Cc/32, Bb), dim3(32, 8)>>>();

    // scores: S[c,d] = (1/C) * q . k   (x3)
    {
        GArgs a = {};
        a.Ah = qkvh; a.Al = qkvl;
        a.Bh = qkvh + (size_t)512*Nn; a.Bl = qkvl + (size_t)512*Nn;
        a.sA = (long long)K3 * Nn; a.sB = (long long)K3 * Nn; a.sC = (long long)Cc * Cc;
        a.lda = Nn; a.ldb = Nn; a.ldc = Cc; a.K = Nn;
        a.Cf = Sf; a.Ch = nullptr; a.Cl = nullptr; a.bias = nullptr; a.scale = 1.0f / (float)Cc;
        gemmh<<<dim3(Cc/128, Cc/128, Bb), 256, G_SMEM>>>(a);
    }
    softmax_split<<<Bb*Cc, 256>>>();

    // PV: Ot[n,c] = sum_d vt[n,d] * P[c,d]   (x3)
    {
        GArgs a = {};
        a.Ah = vth; a.Al = vtl; a.Bh = phh; a.Bl = pll;
        a.sA = (long long)Nn * Cc; a.sB = (long long)Cc * Cc; a.sC = (long long)Nn * Cc;
        a.lda = Cc; a.ldb = Cc; a.ldc = Cc; a.K = Cc;
        a.Cf = nullptr; a.Ch = oth; a.Cl = otl; a.bias = nullptr; a.scale = 1.f;
        gemmh<<<dim3(Cc/128, Nn/128, Bb), 256, G_SMEM>>>(a);
    }

    // proj: y[n,o] = sum_c Ot[n,c] * wproj[o,c] + bias[o]   (x3)
    {
        GArgs a = {};
        a.Ah = oth; a.Al = otl; a.Bh = wph; a.Bl = wpl;
        a.sA = (long long)Nn * Cc; a.sB = 0; a.sC = (long long)Nn * Cc;
        a.lda = Cc; a.ldb = Cc; a.ldc = Cc; a.K = Cc;
        a.Cf = y; a.Ch = nullptr; a.Cl = nullptr; a.bias = bproj; a.scale = 1.f;
        gemmh<<<dim3(Cc/128, Nn/128, Bb), 256, G_SMEM>>>(a);
    }
}

// round 5
// speedup vs baseline: 4.4959x; 1.3113x over previous
#include <cuda_runtime.h>
#include <cuda_fp16.h>
#include <cstdint>

#define Bb 16
#define Nn 2048
#define Cc 512
#define K3 1536

// ---------------- device scratch (no allocations) ----------------
__device__ float  g_w3t [9*512*512];          // [br*3+t][o][i]
__device__ __half g_wh [1536*1536];           // fp16 Weff [br*512+o][t*512+c]
__device__ __half g_wph[512*512];
__device__ __half g_wpl[512*512];
__device__ __half g_xh [50331648];            // [b][n][t*512+c]
__device__ __half g_qkvh[50331648];           // [b][3C][N]
__device__ __half g_qkvl[50331648];
__device__ __half g_vth[16777216];            // [b][n][d]
__device__ __half g_vtl[16777216];
__device__ float  g_S  [4194304];             // [b][c][d]
__device__ __half g_ph [4194304];
__device__ __half g_pl [4194304];
__device__ __half g_oth[16777216];            // [b][n][c]
__device__ __half g_otl[16777216];

// ---------------- PTX helpers ----------------
__device__ __forceinline__ uint32_t s2u(const void* p){
    uint32_t a; asm("{ .reg .u64 t; cvta.to.shared.u64 t, %1; cvt.u32.u64 %0, t; }" : "=r"(a) : "l"(p)); return a;
}
__device__ __forceinline__ void cpa16(uint32_t d, const void* s){
    asm volatile("cp.async.cg.shared.global [%0], [%1], 16;" :: "r"(d), "l"(s));
}
__device__ __forceinline__ void cp_commit(){ asm volatile("cp.async.commit_group;"); }
__device__ __forceinline__ void cp_wait1(){ asm volatile("cp.async.wait_group 1;"); }
__device__ __forceinline__ void cp_wait0(){ asm volatile("cp.async.wait_group 0;"); }
__device__ __forceinline__ void ldsm4(uint32_t& r0, uint32_t& r1, uint32_t& r2, uint32_t& r3, uint32_t a){
    asm volatile("ldmatrix.sync.aligned.m8n8.x4.shared.b16 {%0,%1,%2,%3}, [%4];"
        : "=r"(r0), "=r"(r1), "=r"(r2), "=r"(r3) : "r"(a));
}
__device__ __forceinline__ void mma16816(float* d, const uint32_t* a, uint32_t b0, uint32_t b1){
    asm volatile("mma.sync.aligned.m16n8k16.row.col.f32.f16.f16.f32 "
        "{%0,%1,%2,%3}, {%4,%5,%6,%7}, {%8,%9}, {%0,%1,%2,%3};"
        : "+f"(d[0]), "+f"(d[1]), "+f"(d[2]), "+f"(d[3])
        : "r"(a[0]), "r"(a[1]), "r"(a[2]), "r"(a[3]), "r"(b0), "r"(b1));
}

#define ROWB 80u          // smem bytes per row (32 halves + 8 pad)
#define MATB 10240u       // one 128-row matrix

// =====================================================================
// gemm1h: D = A * B^T, both plain fp16, split-half output. 1 MMA pass.
// CTA 128x128, warps 4Mx2N, K-stage 32, double buffer, 2 CTAs/SM.
// =====================================================================
struct G1Args {
    const __half* A; const __half* B;
    long long sA, sB, sC;
    int lda, ldb, ldc, K;
    __half* Ch; __half* Cl;
};

#define BUF1 20480u
#define G1_SMEM (2*20480)

__global__ __launch_bounds__(256, 2) void gemm1h(const G1Args g) {
    extern __shared__ char smem[];
    uint32_t sb = s2u(smem);
    const int tid  = threadIdx.x;
    const int lane = tid & 31;
    const int wid  = tid >> 5;

    const int b  = blockIdx.z;
    const int m0 = blockIdx.y * 128;
    const int n0 = blockIdx.x * 128;
    const __half* Ap = g.A + (long long)b * g.sA + (long long)m0 * g.lda;
    const __half* Bp = g.B + (long long)b * g.sB + (long long)n0 * g.ldb;

    const int NK = g.K >> 5;

    auto load_chunk = [&](int kc) {
        uint32_t base = sb + (uint32_t)(kc & 1) * BUF1;
        int ko = kc << 5;
        #pragma unroll
        for (int it = 0; it < 2; it++) {
            int u = tid + it * 256;
            int r = u >> 2, cu = u & 3;
            uint32_t off = (uint32_t)r * ROWB + (uint32_t)cu * 16u;
            cpa16(base + off,        Ap + (size_t)r * g.lda + ko + cu * 8);
            cpa16(base + MATB + off, Bp + (size_t)r * g.ldb + ko + cu * 8);
        }
        cp_commit();
    };

    float acc[2][8][4];
    #pragma unroll
    for (int i = 0; i < 2; i++)
        #pragma unroll
        for (int j = 0; j < 8; j++)
            #pragma unroll
            for (int q = 0; q < 4; q++) acc[i][j][q] = 0.f;

    const int m0w = (wid >> 1) * 32;
    const int n0w = (wid & 1) * 64;
    const int l16 = lane & 15, hi = lane >> 4;

    load_chunk(0);
    for (int kc = 0; kc < NK; kc++) {
        if (kc + 1 < NK) { load_chunk(kc + 1); cp_wait1(); }
        else             { cp_wait0(); }
        __syncthreads();

        uint32_t base  = sb + (uint32_t)(kc & 1) * BUF1;
        uint32_t aAddr = base + (uint32_t)(m0w + l16) * ROWB + (uint32_t)hi * 16u;
        uint32_t bAddr = base + MATB + (uint32_t)(n0w + l16) * ROWB + (uint32_t)hi * 16u;

        #pragma unroll
        for (int ks = 0; ks < 2; ks++) {
            uint32_t koff = (uint32_t)ks * 32u;
            uint32_t av[2][4], bv[4][4];
            ldsm4(av[0][0], av[0][1], av[0][2], av[0][3], aAddr + koff);
            ldsm4(av[1][0], av[1][1], av[1][2], av[1][3], aAddr + 16*ROWB + koff);
            #pragma unroll
            for (int nt = 0; nt < 4; nt++)
                ldsm4(bv[nt][0], bv[nt][1], bv[nt][2], bv[nt][3], bAddr + (uint32_t)nt*16*ROWB + koff);
            #pragma unroll
            for (int mi = 0; mi < 2; mi++) {
                #pragma unroll
                for (int nj = 0; nj < 8; nj++) {
                    int nt = nj >> 1, sel = nj & 1;
                    uint32_t b0 = sel ? bv[nt][1] : bv[nt][0];
                    uint32_t b1 = sel ? bv[nt][3] : bv[nt][2];
                    mma16816(acc[mi][nj], av[mi], b0, b1);
                }
            }
        }
        __syncthreads();
    }

    const int rowBase = m0 + m0w + (lane >> 2);
    const int colBase = n0 + n0w + (lane & 3) * 2;
    __half* Ch = g.Ch + (long long)b * g.sC;
    __half* Cl = g.Cl + (long long)b * g.sC;
    #pragma unroll
    for (int mi = 0; mi < 2; mi++) {
        #pragma unroll
        for (int nj = 0; nj < 8; nj++) {
            int c = colBase + nj * 8;
            #pragma unroll
            for (int half = 0; half < 2; half++) {
                int r = rowBase + mi * 16 + half * 8;
                float v0 = acc[mi][nj][half*2 + 0];
                float v1 = acc[mi][nj][half*2 + 1];
                __half h0 = __float2half_rn(v0), h1 = __float2half_rn(v1);
                __half l0 = __float2half_rn(v0 - __half2float(h0));
                __half l1 = __float2half_rn(v1 - __half2float(h1));
                *(__half2*)(Ch + (long long)r * g.ldc + c) = __halves2half2(h0, h1);
                *(__half2*)(Cl + (long long)r * g.ldc + c) = __halves2half2(l0, l1);
            }
        }
    }
}

// =====================================================================
// gemmh: x3-split GEMM for scores / PV / proj (unchanged)
// =====================================================================
struct GArgs {
    const __half* Ah; const __half* Al;
    const __half* Bh; const __half* Bl;
    long long sA, sB, sC;
    int lda, ldb, ldc, K;
    float* Cf; __half* Ch; __half* Cl;
    const float* bias;
    float scale;
};

#define BUFB 40960u
#define G_SMEM (2*40960)

__global__ __launch_bounds__(256, 1) void gemmh(const GArgs g) {
    extern __shared__ char smem[];
    uint32_t sb = s2u(smem);
    const int tid  = threadIdx.x;
    const int lane = tid & 31;
    const int wid  = tid >> 5;

    const int b  = blockIdx.z;
    const int m0 = blockIdx.y * 128;
    const int n0 = blockIdx.x * 128;
    const __half* Ah = g.Ah + (long long)b * g.sA + (long long)m0 * g.lda;
    const __half* Al = g.Al + (long long)b * g.sA + (long long)m0 * g.lda;
    const __half* Bh = g.Bh + (long long)b * g.sB + (long long)n0 * g.ldb;
    const __half* Bl = g.Bl + (long long)b * g.sB + (long long)n0 * g.ldb;

    const int NK = g.K >> 5;

    auto load_chunk = [&](int kc) {
        uint32_t base = sb + (uint32_t)(kc & 1) * BUFB;
        int ko = kc << 5;
        #pragma unroll
        for (int it = 0; it < 2; it++) {
            int u = tid + it * 256;
            int r = u >> 2, cu = u & 3;
            uint32_t off = (uint32_t)r * ROWB + (uint32_t)cu * 16u;
            cpa16(base + off,          Ah + (size_t)r * g.lda + ko + cu * 8);
            cpa16(base + MATB + off,   Al + (size_t)r * g.lda + ko + cu * 8);
            cpa16(base + 2*MATB + off, Bh + (size_t)r * g.ldb + ko + cu * 8);
            cpa16(base + 3*MATB + off, Bl + (size_t)r * g.ldb + ko + cu * 8);
        }
        cp_commit();
    };

    float acc[2][8][4];
    #pragma unroll
    for (int i = 0; i < 2; i++)
        #pragma unroll
        for (int j = 0; j < 8; j++)
            #pragma unroll
            for (int q = 0; q < 4; q++) acc[i][j][q] = 0.f;

    const int m0w = (wid >> 1) * 32;
    const int n0w = (wid & 1) * 64;
    const int l16 = lane & 15, hi = lane >> 4;

    load_chunk(0);
    for (int kc = 0; kc < NK; kc++) {
        if (kc + 1 < NK) { load_chunk(kc + 1); cp_wait1(); }
        else             { cp_wait0(); }
        __syncthreads();

        uint32_t base  = sb + (uint32_t)(kc & 1) * BUFB;
        uint32_t aAddr = base + (uint32_t)(m0w + l16) * ROWB + (uint32_t)hi * 16u;
        uint32_t bAddr = base + 2*MATB + (uint32_t)(n0w + l16) * ROWB + (uint32_t)hi * 16u;

        #pragma unroll
        for (int ks = 0; ks < 2; ks++) {
            uint32_t koff = (uint32_t)ks * 32u;
            uint32_t ah[2][4], al[2][4], bh[4][4], bl[4][4];
            ldsm4(ah[0][0], ah[0][1], ah[0][2], ah[0][3], aAddr + koff);
            ldsm4(ah[1][0], ah[1][1], ah[1][2], ah[1][3], aAddr + 16*ROWB + koff);
            ldsm4(al[0][0], al[0][1], al[0][2], al[0][3], aAddr + MATB + koff);
            ldsm4(al[1][0], al[1][1], al[1][2], al[1][3], aAddr + MATB + 16*ROWB + koff);
            #pragma unroll
            for (int nt = 0; nt < 4; nt++) {
                ldsm4(bh[nt][0], bh[nt][1], bh[nt][2], bh[nt][3], bAddr + (uint32_t)nt*16*ROWB + koff);
                ldsm4(bl[nt][0], bl[nt][1], bl[nt][2], bl[nt][3], bAddr + MATB + (uint32_t)nt*16*ROWB + koff);
            }
            #pragma unroll
            for (int mi = 0; mi < 2; mi++) {
                #pragma unroll
                for (int nj = 0; nj < 8; nj++) {
                    int nt = nj >> 1, sel = nj & 1;
                    uint32_t bh0 = sel ? bh[nt][1] : bh[nt][0];
                    uint32_t bh1 = sel ? bh[nt][3] : bh[nt][2];
                    uint32_t bl0 = sel ? bl[nt][1] : bl[nt][0];
                    uint32_t bl1 = sel ? bl[nt][3] : bl[nt][2];
                    mma16816(acc[mi][nj], ah[mi], bh0, bh1);
                    mma16816(acc[mi][nj], ah[mi], bl0, bl1);
                    mma16816(acc[mi][nj], al[mi], bh0, bh1);
                }
            }
        }
        __syncthreads();
    }

    const int rowBase = m0 + m0w + (lane >> 2);
    const int colBase = n0 + n0w + (lane & 3) * 2;
    if (g.Cf) {
        float* C = g.Cf + (long long)b * g.sC;
        #pragma unroll
        for (int mi = 0; mi < 2; mi++) {
            #pragma unroll
            for (int nj = 0; nj < 8; nj++) {
                int c = colBase + nj * 8;
                #pragma unroll
                for (int half = 0; half < 2; half++) {
                    int r = rowBase + mi * 16 + half * 8;
                    float2 v;
                    v.x = acc[mi][nj][half*2 + 0] * g.scale;
                    v.y = acc[mi][nj][half*2 + 1] * g.scale;
                    if (g.bias) { v.x += g.bias[c]; v.y += g.bias[c + 1]; }
                    *(float2*)(C + (long long)r * g.ldc + c) = v;
                }
            }
        }
    } else {
        __half* Ch = g.Ch + (long long)b * g.sC;
        __half* Cl = g.Cl + (long long)b * g.sC;
        #pragma unroll
        for (int mi = 0; mi < 2; mi++) {
            #pragma unroll
            for (int nj = 0; nj < 8; nj++) {
                int c = colBase + nj * 8;
                #pragma unroll
                for (int half = 0; half < 2; half++) {
                    int r = rowBase + mi * 16 + half * 8;
                    float v0 = acc[mi][nj][half*2 + 0];
                    float v1 = acc[mi][nj][half*2 + 1];
                    __half h0 = __float2half_rn(v0), h1 = __float2half_rn(v1);
                    __half l0 = __float2half_rn(v0 - __half2float(h0));
                    __half l1 = __float2half_rn(v1 - __half2float(h1));
                    *(__half2*)(Ch + (long long)r * g.ldc + c) = __halves2half2(h0, h1);
                    *(__half2*)(Cl + (long long)r * g.ldc + c) = __halves2half2(l0, l1);
                }
            }
        }
    }
}

// ---------------- w3 transpose ----------------
__global__ __launch_bounds__(256) void w3t_kernel(const float* __restrict__ w3q,
                                                  const float* __restrict__ w3k,
                                                  const float* __restrict__ w3v) {
    int oi = blockIdx.x * 256 + threadIdx.x;
    int br = blockIdx.y;
    const float* w3 = br == 0 ? w3q : br == 1 ? w3k : w3v;
    float a = w3[(size_t)oi*3 + 0];
    float b = w3[(size_t)oi*3 + 1];
    float c = w3[(size_t)oi*3 + 2];
    g_w3t[(size_t)(br*3 + 0)*262144 + oi] = a;
    g_w3t[(size_t)(br*3 + 1)*262144 + oi] = b;
    g_w3t[(size_t)(br*3 + 2)*262144 + oi] = c;
}

// ---------------- weff (fp32 SIMT, fp16 output) ----------------
__global__ __launch_bounds__(256) void weff2(const float* __restrict__ w1q,
                                             const float* __restrict__ w1k,
                                             const float* __restrict__ w1v) {
    int z = blockIdx.z;
    int br = z / 3, t = z - br*3;
    const float* A  = g_w3t + (size_t)z * 262144;
    const float* w1 = br == 0 ? w1q : br == 1 ? w1k : w1v;
    int n0 = blockIdx.x * 64, m0 = blockIdx.y * 64;
    __shared__ float As[64][17];
    __shared__ float Bs[16][64];
    int tid = threadIdx.x;
    int tx = tid & 15, ty = tid >> 4;
    float acc[4][4] = {};
    for (int k0 = 0; k0 < 512; k0 += 16) {
        {
            int kk = tid & 15, mmb = tid >> 4;
            #pragma unroll
            for (int j = 0; j < 4; j++) {
                int mm = mmb + j*16;
                As[mm][kk] = A[(size_t)(m0+mm)*512 + k0 + kk];
            }
        }
        {
            int nn = tid & 63, kkb = tid >> 6;
            #pragma unroll
            for (int j = 0; j < 4; j++) {
                int kk = kkb + j*4;
                Bs[kk][nn] = w1[(size_t)(k0+kk)*512 + n0 + nn];
            }
        }
        __syncthreads();
        #pragma unroll
        for (int kk = 0; kk < 16; kk++) {
            float a[4];
            #pragma unroll
            for (int i = 0; i < 4; i++) a[i] = As[ty*4+i][kk];
            float4 bv = *(const float4*)&Bs[kk][tx*4];
            float bf[4] = {bv.x, bv.y, bv.z, bv.w};
            #pragma unroll
            for (int i = 0; i < 4; i++)
                #pragma unroll
                for (int j = 0; j < 4; j++) acc[i][j] += a[i]*bf[j];
        }
        __syncthreads();
    }
    #pragma unroll
    for (int i = 0; i < 4; i++) {
        int o = m0 + ty*4 + i;
        #pragma unroll
        for (int j = 0; j < 4; j++) {
            int c = n0 + tx*4 + j;
            g_wh[(size_t)(br*512 + o)*K3 + t*512 + c] = __float2half_rn(acc[i][j]);
        }
    }
}

// ---------------- split wproj ----------------
__global__ __launch_bounds__(256) void split_wproj(const float* __restrict__ w) {
    size_t i = (size_t)blockIdx.x * 256 + threadIdx.x;
    float v = w[i];
    __half h = __float2half_rn(v);
    g_wph[i] = h; g_wpl[i] = __float2half_rn(v - __half2float(h));
}

// ---------------- Xmat build (hi only) ----------------
__global__ __launch_bounds__(256) void build_xmat(const float* __restrict__ x) {
    int b = blockIdx.y, n = blockIdx.x;
    size_t dst = ((size_t)b * Nn + n) * K3;
    #pragma unroll
    for (int t = 0; t < 3; t++) {
        int ns = n + t - 1;
        if (ns < 0) ns += Nn; else if (ns >= Nn) ns -= Nn;
        const float* row = x + ((size_t)b * Nn + ns) * Cc;
        for (int c = threadIdx.x; c < Cc; c += 256)
            g_xh[dst + t*Cc + c] = __float2half_rn(row[c]);
    }
}

// ---------------- v transpose ----------------
__global__ __launch_bounds__(256) void vtrans() {
    __shared__ __half t0[32][33];
    __shared__ __half t1[32][33];
    int b = blockIdx.z;
    int n0 = blockIdx.x * 32, d0 = blockIdx.y * 32;
    int tx = threadIdx.x, ty = threadIdx.y;
    const __half* sh = g_qkvh + (size_t)b*K3*Nn + (size_t)(1024 + d0)*Nn + n0;
    const __half* sl = g_qkvl + (size_t)b*K3*Nn + (size_t)(1024 + d0)*Nn + n0;
    #pragma unroll
    for (int i = 0; i < 32; i += 8) {
        t0[ty+i][tx] = sh[(size_t)(ty+i)*Nn + tx];
        t1[ty+i][tx] = sl[(size_t)(ty+i)*Nn + tx];
    }
    __syncthreads();
    __half* dh = g_vth + (size_t)b*Nn*Cc;
    __half* dl = g_vtl + (size_t)b*Nn*Cc;
    #pragma unroll
    for (int i = 0; i < 32; i += 8) {
        dh[(size_t)(n0+ty+i)*Cc + d0 + tx] = t0[tx][ty+i];
        dl[(size_t)(n0+ty+i)*Cc + d0 + tx] = t1[tx][ty+i];
    }
}

// ---------------- softmax -> split P ----------------
__global__ __launch_bounds__(256) void softmax_split() {
    size_t row = blockIdx.x;
    const float* p = g_S + row * Cc;
    int tid = threadIdx.x;
    float v0 = p[tid], v1 = p[tid + 256];
    float m = fmaxf(v0, v1);
    __shared__ float red[8];
    #pragma unroll
    for (int o = 16; o > 0; o >>= 1) m = fmaxf(m, __shfl_xor_sync(0xffffffffu, m, o));
    if ((tid & 31) == 0) red[tid >> 5] = m;
    __syncthreads();
    float mm = red[0];
    #pragma unroll
    for (int i = 1; i < 8; i++) mm = fmaxf(mm, red[i]);
    float e0 = __expf(v0 - mm), e1 = __expf(v1 - mm);
    float s = e0 + e1;
    #pragma unroll
    for (int o = 16; o > 0; o >>= 1) s += __shfl_xor_sync(0xffffffffu, s, o);
    __syncthreads();
    if ((tid & 31) == 0) red[tid >> 5] = s;
    __syncthreads();
    float ss = 0.f;
    #pragma unroll
    for (int i = 0; i < 8; i++) ss += red[i];
    float inv = 1.0f / ss;
    float q0 = e0 * inv, q1 = e1 * inv;
    __half h0 = __float2half_rn(q0), h1 = __float2half_rn(q1);
    g_ph[row*Cc + tid]       = h0;
    g_pl[row*Cc + tid]       = __float2half_rn(q0 - __half2float(h0));
    g_ph[row*Cc + tid + 256] = h1;
    g_pl[row*Cc + tid + 256] = __float2half_rn(q1 - __half2float(h1));
}

// ---------------- launch ----------------
static void* sym(const void* s) { void* p = nullptr; cudaGetSymbolAddress(&p, s); return p; }

extern "C" void kernel_launch(void* const* d_in, const int* in_sizes, int n_in,
                              void* d_out, int out_size) {
    const float* x     = (const float*)d_in[0];
    const float* w1q   = (const float*)d_in[1];
    const float* w3q   = (const float*)d_in[2];
    const float* w1k   = (const float*)d_in[3];
    const float* w3k   = (const float*)d_in[4];
    const float* w1v   = (const float*)d_in[5];
    const float* w3v   = (const float*)d_in[6];
    const float* wproj = (const float*)d_in[7];
    const float* bproj = (const float*)d_in[8];
    float* y = (float*)d_out;

    cudaFuncSetAttribute(gemmh,  cudaFuncAttributeMaxDynamicSharedMemorySize, G_SMEM);
    cudaFuncSetAttribute(gemm1h, cudaFuncAttributeMaxDynamicSharedMemorySize, G1_SMEM);

    __half* wh   = (__half*)sym(g_wh);
    __half* wph  = (__half*)sym(g_wph);    __half* wpl  = (__half*)sym(g_wpl);
    __half* xh   = (__half*)sym(g_xh);
    __half* qkvh = (__half*)sym(g_qkvh);   __half* qkvl = (__half*)sym(g_qkvl);
    __half* vth  = (__half*)sym(g_vth);    __half* vtl  = (__half*)sym(g_vtl);
    float*  Sf   = (float*) sym(g_S);
    __half* phh  = (__half*)sym(g_ph);     __half* pll  = (__half*)sym(g_pl);
    __half* oth  = (__half*)sym(g_oth);    __half* otl  = (__half*)sym(g_otl);

    // weights prep
    w3t_kernel<<<dim3(1024, 3), 256>>>(w3q, w3k, w3v);
    weff2<<<dim3(8, 8, 9), 256>>>(w1q, w1k, w1v);
    split_wproj<<<1024, 256>>>(wproj);
    build_xmat<<<dim3(Nn, Bb), 256>>>(x);

    // QKV (single pass, fp16 x fp16, split output): [3C x N] = Weff * Xmat^T
    {
        G1Args a = {};
        a.A = wh; a.B = xh;
        a.sA = 0; a.sB = (long long)Nn * K3; a.sC = (long long)K3 * Nn;
        a.lda = K3; a.ldb = K3; a.ldc = Nn; a.K = K3;
        a.Ch = qkvh; a.Cl = qkvl;
        gemm1h<<<dim3(Nn/128, K3/128, Bb), 256, G1_SMEM>>>(a);
    }
    vtrans<<<dim3(Nn/32, Cc/32, Bb), dim3(32, 8)>>>();

    // scores: S[c,d] = (1/C) * q . k   (x3)
    {
        GArgs a = {};
        a.Ah = qkvh; a.Al = qkvl;
        a.Bh = qkvh + (size_t)512*Nn; a.Bl = qkvl + (size_t)512*Nn;
        a.sA = (long long)K3 * Nn; a.sB = (long long)K3 * Nn; a.sC = (long long)Cc * Cc;
        a.lda = Nn; a.ldb = Nn; a.ldc = Cc; a.K = Nn;
        a.Cf = Sf; a.Ch = nullptr; a.Cl = nullptr; a.bias = nullptr; a.scale = 1.0f / (float)Cc;
        gemmh<<<dim3(Cc/128, Cc/128, Bb), 256, G_SMEM>>>(a);
    }
    softmax_split<<<Bb*Cc, 256>>>();

    // PV: Ot[n,c] = sum_d vt[n,d] * P[c,d]   (x3)
    {
        GArgs a = {};
        a.Ah = vth; a.Al = vtl; a.Bh = phh; a.Bl = pll;
        a.sA = (long long)Nn * Cc; a.sB = (long long)Cc * Cc; a.sC = (long long)Nn * Cc;
        a.lda = Cc; a.ldb = Cc; a.ldc = Cc; a.K = Cc;
        a.Cf = nullptr; a.Ch = oth; a.Cl = otl; a.bias = nullptr; a.scale = 1.f;
        gemmh<<<dim3(Cc/128, Nn/128, Bb), 256, G_SMEM>>>(a);
    }

    // proj: y[n,o] = sum_c Ot[n,c] * wproj[o,c] + bias[o]   (x3)
    {
        GArgs a = {};
        a.Ah = oth; a.Al = otl; a.Bh = wph; a.Bl = wpl;
        a.sA = (long long)Nn * Cc; a.sB = 0; a.sC = (long long)Nn * Cc;
        a.lda = Cc; a.ldb = Cc; a.ldc = Cc; a.K = Cc;
        a.Cf = y; a.Ch = nullptr; a.Cl = nullptr; a.bias = bproj; a.scale = 1.f;
        gemmh<<<dim3(Cc/128, Nn/128, Bb), 256, G_SMEM>>>(a);
    }
}

// round 6
// speedup vs baseline: 6.6623x; 1.4819x over previous
#include <cuda_runtime.h>
#include <cuda_fp16.h>
#include <cstdint>

#define Bb 16
#define Nn 2048
#define Cc 512
#define K3 1536

// ---------------- device scratch ----------------
__device__ float  g_w3t [9*512*512];   // [br*3+t][o][i]
__device__ __half g_wh  [1536*1536];   // fp16 Weff [br*512+o][t*512+c]
__device__ __half g_wph [512*512];     // fp16 wproj
__device__ __half g_xh  [16777216];    // [b][n][c] fp16 x
__device__ __half g_qkv [50331648];    // [b][3C][N]
__device__ __half g_vt  [16777216];    // [b][n][d]
__device__ float  g_S   [4194304];     // [b][c][d]
__device__ __half g_p   [4194304];     // softmax(S) fp16
__device__ __half g_ot  [16777216];    // [b][n][c]

// ---------------- PTX helpers ----------------
__device__ __forceinline__ uint32_t s2u(const void* p){
    uint32_t a; asm("{ .reg .u64 t; cvta.to.shared.u64 t, %1; cvt.u32.u64 %0, t; }" : "=r"(a) : "l"(p)); return a;
}
__device__ __forceinline__ void cpa16(uint32_t d, const void* s){
    asm volatile("cp.async.cg.shared.global [%0], [%1], 16;" :: "r"(d), "l"(s));
}
__device__ __forceinline__ void cp_commit(){ asm volatile("cp.async.commit_group;"); }
__device__ __forceinline__ void cp_wait1(){ asm volatile("cp.async.wait_group 1;"); }
__device__ __forceinline__ void cp_wait0(){ asm volatile("cp.async.wait_group 0;"); }
__device__ __forceinline__ void ldsm4(uint32_t& r0, uint32_t& r1, uint32_t& r2, uint32_t& r3, uint32_t a){
    asm volatile("ldmatrix.sync.aligned.m8n8.x4.shared.b16 {%0,%1,%2,%3}, [%4];"
        : "=r"(r0), "=r"(r1), "=r"(r2), "=r"(r3) : "r"(a));
}
__device__ __forceinline__ void mma16816(float* d, const uint32_t* a, uint32_t b0, uint32_t b1){
    asm volatile("mma.sync.aligned.m16n8k16.row.col.f32.f16.f16.f32 "
        "{%0,%1,%2,%3}, {%4,%5,%6,%7}, {%8,%9}, {%0,%1,%2,%3};"
        : "+f"(d[0]), "+f"(d[1]), "+f"(d[2]), "+f"(d[3])
        : "r"(a[0]), "r"(a[1]), "r"(a[2]), "r"(a[3]), "r"(b0), "r"(b1));
}

#define ROWB 80u
#define MATB 10240u
#define BUF1 20480u
#define G1_SMEM (2*20480)

// =====================================================================
// MMA core shared by all GEMMs (CTA 128x128, warps 4Mx2N, K-stage 32)
// =====================================================================
struct Frag { float acc[2][8][4]; };

__device__ __forceinline__ void mma_stage(uint32_t base, int m0w, int n0w, int l16, int hi,
                                          float acc[2][8][4]) {
    uint32_t aAddr = base + (uint32_t)(m0w + l16) * ROWB + (uint32_t)hi * 16u;
    uint32_t bAddr = base + MATB + (uint32_t)(n0w + l16) * ROWB + (uint32_t)hi * 16u;
    #pragma unroll
    for (int ks = 0; ks < 2; ks++) {
        uint32_t koff = (uint32_t)ks * 32u;
        uint32_t av[2][4], bv[4][4];
        ldsm4(av[0][0], av[0][1], av[0][2], av[0][3], aAddr + koff);
        ldsm4(av[1][0], av[1][1], av[1][2], av[1][3], aAddr + 16*ROWB + koff);
        #pragma unroll
        for (int nt = 0; nt < 4; nt++)
            ldsm4(bv[nt][0], bv[nt][1], bv[nt][2], bv[nt][3], bAddr + (uint32_t)nt*16*ROWB + koff);
        #pragma unroll
        for (int mi = 0; mi < 2; mi++) {
            #pragma unroll
            for (int nj = 0; nj < 8; nj++) {
                int nt = nj >> 1, sel = nj & 1;
                uint32_t b0 = sel ? bv[nt][1] : bv[nt][0];
                uint32_t b1 = sel ? bv[nt][3] : bv[nt][2];
                mma16816(acc[mi][nj], av[mi], b0, b1);
            }
        }
    }
}

// =====================================================================
// gemm_qkv: QKV with fused circular shift in the B loader.
// D[o, n] = sum_{k=(t,c)} Weff[o,k] * xh[b][(n+t-1)%N][c]; fp16 out [3C][N]
// =====================================================================
__global__ __launch_bounds__(256, 2) void gemm_qkv() {
    extern __shared__ char smem[];
    uint32_t sb = s2u(smem);
    const int tid  = threadIdx.x;
    const int lane = tid & 31;
    const int wid  = tid >> 5;

    const int b  = blockIdx.z;
    const int m0 = blockIdx.y * 128;
    const int n0 = blockIdx.x * 128;
    const __half* Ap = g_wh + (size_t)m0 * K3;
    const __half* Xb = g_xh + (size_t)b * Nn * Cc;

    const int NK = K3 >> 5;   // 48

    auto load_chunk = [&](int kc) {
        uint32_t base = sb + (uint32_t)(kc & 1) * BUF1;
        int ko = kc << 5;
        int t  = ko >> 9;            // constant within chunk
        int c0 = ko & 511;
        #pragma unroll
        for (int it = 0; it < 2; it++) {
            int u = tid + it * 256;
            int r = u >> 2, cu = u & 3;
            uint32_t off = (uint32_t)r * ROWB + (uint32_t)cu * 16u;
            cpa16(base + off, Ap + (size_t)r * K3 + ko + cu * 8);
            int n = n0 + r + t - 1;
            if (n < 0) n += Nn; else if (n >= Nn) n -= Nn;
            cpa16(base + MATB + off, Xb + (size_t)n * Cc + c0 + cu * 8);
        }
        cp_commit();
    };

    float acc[2][8][4];
    #pragma unroll
    for (int i = 0; i < 2; i++)
        #pragma unroll
        for (int j = 0; j < 8; j++)
            #pragma unroll
            for (int q = 0; q < 4; q++) acc[i][j][q] = 0.f;

    const int m0w = (wid >> 1) * 32;
    const int n0w = (wid & 1) * 64;
    const int l16 = lane & 15, hi = lane >> 4;

    load_chunk(0);
    for (int kc = 0; kc < NK; kc++) {
        if (kc + 1 < NK) { load_chunk(kc + 1); cp_wait1(); }
        else             { cp_wait0(); }
        __syncthreads();
        mma_stage(sb + (uint32_t)(kc & 1) * BUF1, m0w, n0w, l16, hi, acc);
        __syncthreads();
    }

    const int rowBase = m0 + m0w + (lane >> 2);
    const int colBase = n0 + n0w + (lane & 3) * 2;
    __half* C = g_qkv + (size_t)b * K3 * Nn;
    #pragma unroll
    for (int mi = 0; mi < 2; mi++) {
        #pragma unroll
        for (int nj = 0; nj < 8; nj++) {
            int c = colBase + nj * 8;
            #pragma unroll
            for (int half = 0; half < 2; half++) {
                int r = rowBase + mi * 16 + half * 8;
                *(__half2*)(C + (size_t)r * Nn + c) =
                    __halves2half2(__float2half_rn(acc[mi][nj][half*2]),
                                   __float2half_rn(acc[mi][nj][half*2+1]));
            }
        }
    }
}

// =====================================================================
// gemm1: generic plain-fp16 GEMM. D = A * B^T.
// Out: fp32 (scale + optional bias) if Cf != null, else fp16.
// =====================================================================
struct G1Args {
    const __half* A; const __half* B;
    long long sA, sB, sC;
    int lda, ldb, ldc, K;
    float* Cf; __half* Ch;
    const float* bias;
    float scale;
};

__global__ __launch_bounds__(256, 2) void gemm1(const G1Args g) {
    extern __shared__ char smem[];
    uint32_t sb = s2u(smem);
    const int tid  = threadIdx.x;
    const int lane = tid & 31;
    const int wid  = tid >> 5;

    const int b  = blockIdx.z;
    const int m0 = blockIdx.y * 128;
    const int n0 = blockIdx.x * 128;
    const __half* Ap = g.A + (long long)b * g.sA + (long long)m0 * g.lda;
    const __half* Bp = g.B + (long long)b * g.sB + (long long)n0 * g.ldb;

    const int NK = g.K >> 5;

    auto load_chunk = [&](int kc) {
        uint32_t base = sb + (uint32_t)(kc & 1) * BUF1;
        int ko = kc << 5;
        #pragma unroll
        for (int it = 0; it < 2; it++) {
            int u = tid + it * 256;
            int r = u >> 2, cu = u & 3;
            uint32_t off = (uint32_t)r * ROWB + (uint32_t)cu * 16u;
            cpa16(base + off,        Ap + (size_t)r * g.lda + ko + cu * 8);
            cpa16(base + MATB + off, Bp + (size_t)r * g.ldb + ko + cu * 8);
        }
        cp_commit();
    };

    float acc[2][8][4];
    #pragma unroll
    for (int i = 0; i < 2; i++)
        #pragma unroll
        for (int j = 0; j < 8; j++)
            #pragma unroll
            for (int q = 0; q < 4; q++) acc[i][j][q] = 0.f;

    const int m0w = (wid >> 1) * 32;
    const int n0w = (wid & 1) * 64;
    const int l16 = lane & 15, hi = lane >> 4;

    load_chunk(0);
    for (int kc = 0; kc < NK; kc++) {
        if (kc + 1 < NK) { load_chunk(kc + 1); cp_wait1(); }
        else             { cp_wait0(); }
        __syncthreads();
        mma_stage(sb + (uint32_t)(kc & 1) * BUF1, m0w, n0w, l16, hi, acc);
        __syncthreads();
    }

    const int rowBase = m0 + m0w + (lane >> 2);
    const int colBase = n0 + n0w + (lane & 3) * 2;
    if (g.Cf) {
        float* C = g.Cf + (long long)b * g.sC;
        #pragma unroll
        for (int mi = 0; mi < 2; mi++) {
            #pragma unroll
            for (int nj = 0; nj < 8; nj++) {
                int c = colBase + nj * 8;
                #pragma unroll
                for (int half = 0; half < 2; half++) {
                    int r = rowBase + mi * 16 + half * 8;
                    float2 v;
                    v.x = acc[mi][nj][half*2 + 0] * g.scale;
                    v.y = acc[mi][nj][half*2 + 1] * g.scale;
                    if (g.bias) { v.x += g.bias[c]; v.y += g.bias[c + 1]; }
                    *(float2*)(C + (long long)r * g.ldc + c) = v;
                }
            }
        }
    } else {
        __half* C = g.Ch + (long long)b * g.sC;
        #pragma unroll
        for (int mi = 0; mi < 2; mi++) {
            #pragma unroll
            for (int nj = 0; nj < 8; nj++) {
                int c = colBase + nj * 8;
                #pragma unroll
                for (int half = 0; half < 2; half++) {
                    int r = rowBase + mi * 16 + half * 8;
                    *(__half2*)(C + (long long)r * g.ldc + c) =
                        __halves2half2(__float2half_rn(acc[mi][nj][half*2]),
                                       __float2half_rn(acc[mi][nj][half*2+1]));
                }
            }
        }
    }
}

// ---------------- w3 transpose ----------------
__global__ __launch_bounds__(256) void w3t_kernel(const float* __restrict__ w3q,
                                                  const float* __restrict__ w3k,
                                                  const float* __restrict__ w3v) {
    int oi = blockIdx.x * 256 + threadIdx.x;
    int br = blockIdx.y;
    const float* w3 = br == 0 ? w3q : br == 1 ? w3k : w3v;
    float a = w3[(size_t)oi*3 + 0];
    float b = w3[(size_t)oi*3 + 1];
    float c = w3[(size_t)oi*3 + 2];
    g_w3t[(size_t)(br*3 + 0)*262144 + oi] = a;
    g_w3t[(size_t)(br*3 + 1)*262144 + oi] = b;
    g_w3t[(size_t)(br*3 + 2)*262144 + oi] = c;
}

// ---------------- weff (fp32 SIMT, fp16 output) ----------------
__global__ __launch_bounds__(256) void weff2(const float* __restrict__ w1q,
                                             const float* __restrict__ w1k,
                                             const float* __restrict__ w1v) {
    int z = blockIdx.z;
    int br = z / 3, t = z - br*3;
    const float* A  = g_w3t + (size_t)z * 262144;
    const float* w1 = br == 0 ? w1q : br == 1 ? w1k : w1v;
    int n0 = blockIdx.x * 64, m0 = blockIdx.y * 64;
    __shared__ float As[64][17];
    __shared__ float Bs[16][64];
    int tid = threadIdx.x;
    int tx = tid & 15, ty = tid >> 4;
    float acc[4][4] = {};
    for (int k0 = 0; k0 < 512; k0 += 16) {
        {
            int kk = tid & 15, mmb = tid >> 4;
            #pragma unroll
            for (int j = 0; j < 4; j++) {
                int mm = mmb + j*16;
                As[mm][kk] = A[(size_t)(m0+mm)*512 + k0 + kk];
            }
        }
        {
            int nn = tid & 63, kkb = tid >> 6;
            #pragma unroll
            for (int j = 0; j < 4; j++) {
                int kk = kkb + j*4;
                Bs[kk][nn] = w1[(size_t)(k0+kk)*512 + n0 + nn];
            }
        }
        __syncthreads();
        #pragma unroll
        for (int kk = 0; kk < 16; kk++) {
            float a[4];
            #pragma unroll
            for (int i = 0; i < 4; i++) a[i] = As[ty*4+i][kk];
            float4 bv = *(const float4*)&Bs[kk][tx*4];
            float bf[4] = {bv.x, bv.y, bv.z, bv.w};
            #pragma unroll
            for (int i = 0; i < 4; i++)
                #pragma unroll
                for (int j = 0; j < 4; j++) acc[i][j] += a[i]*bf[j];
        }
        __syncthreads();
    }
    #pragma unroll
    for (int i = 0; i < 4; i++) {
        int o = m0 + ty*4 + i;
        #pragma unroll
        for (int j = 0; j < 4; j++) {
            int c = n0 + tx*4 + j;
            g_wh[(size_t)(br*512 + o)*K3 + t*512 + c] = __float2half_rn(acc[i][j]);
        }
    }
}

// ---------------- converts ----------------
__global__ __launch_bounds__(256) void conv_wproj(const float* __restrict__ w) {
    size_t i = (size_t)blockIdx.x * 256 + threadIdx.x;
    g_wph[i] = __float2half_rn(w[i]);
}
__global__ __launch_bounds__(256) void conv_x(const float* __restrict__ x) {
    size_t i = (size_t)blockIdx.x * 256 + threadIdx.x;
    float2 v = *(const float2*)(x + i * 2);
    *(__half2*)(g_xh + i * 2) = __halves2half2(__float2half_rn(v.x), __float2half_rn(v.y));
}

// ---------------- v transpose: vt[b][n][d] = qkv[b][1024+d][n] ----------------
__global__ __launch_bounds__(256) void vtrans() {
    __shared__ __half t0[32][33];
    int b = blockIdx.z;
    int n0 = blockIdx.x * 32, d0 = blockIdx.y * 32;
    int tx = threadIdx.x, ty = threadIdx.y;
    const __half* sh = g_qkv + (size_t)b*K3*Nn + (size_t)(1024 + d0)*Nn + n0;
    #pragma unroll
    for (int i = 0; i < 32; i += 8)
        t0[ty+i][tx] = sh[(size_t)(ty+i)*Nn + tx];
    __syncthreads();
    __half* dh = g_vt + (size_t)b*Nn*Cc;
    #pragma unroll
    for (int i = 0; i < 32; i += 8)
        dh[(size_t)(n0+ty+i)*Cc + d0 + tx] = t0[tx][ty+i];
}

// ---------------- softmax -> fp16 P ----------------
__global__ __launch_bounds__(256) void softmax_p() {
    size_t row = blockIdx.x;
    const float* p = g_S + row * Cc;
    int tid = threadIdx.x;
    float v0 = p[tid], v1 = p[tid + 256];
    float m = fmaxf(v0, v1);
    __shared__ float red[8];
    #pragma unroll
    for (int o = 16; o > 0; o >>= 1) m = fmaxf(m, __shfl_xor_sync(0xffffffffu, m, o));
    if ((tid & 31) == 0) red[tid >> 5] = m;
    __syncthreads();
    float mm = red[0];
    #pragma unroll
    for (int i = 1; i < 8; i++) mm = fmaxf(mm, red[i]);
    float e0 = __expf(v0 - mm), e1 = __expf(v1 - mm);
    float s = e0 + e1;
    #pragma unroll
    for (int o = 16; o > 0; o >>= 1) s += __shfl_xor_sync(0xffffffffu, s, o);
    __syncthreads();
    if ((tid & 31) == 0) red[tid >> 5] = s;
    __syncthreads();
    float ss = 0.f;
    #pragma unroll
    for (int i = 0; i < 8; i++) ss += red[i];
    float inv = 1.0f / ss;
    g_p[row*Cc + tid]       = __float2half_rn(e0 * inv);
    g_p[row*Cc + tid + 256] = __float2half_rn(e1 * inv);
}

// ---------------- launch ----------------
static void* sym(const void* s) { void* p = nullptr; cudaGetSymbolAddress(&p, s); return p; }

extern "C" void kernel_launch(void* const* d_in, const int* in_sizes, int n_in,
                              void* d_out, int out_size) {
    const float* x     = (const float*)d_in[0];
    const float* w1q   = (const float*)d_in[1];
    const float* w3q   = (const float*)d_in[2];
    const float* w1k   = (const float*)d_in[3];
    const float* w3k   = (const float*)d_in[4];
    const float* w1v   = (const float*)d_in[5];
    const float* w3v   = (const float*)d_in[6];
    const float* wproj = (const float*)d_in[7];
    const float* bproj = (const float*)d_in[8];
    float* y = (float*)d_out;

    cudaFuncSetAttribute(gemm_qkv, cudaFuncAttributeMaxDynamicSharedMemorySize, G1_SMEM);
    cudaFuncSetAttribute(gemm1,    cudaFuncAttributeMaxDynamicSharedMemorySize, G1_SMEM);

    __half* qkv = (__half*)sym(g_qkv);
    __half* vt  = (__half*)sym(g_vt);
    float*  Sf  = (float*) sym(g_S);
    __half* pp  = (__half*)sym(g_p);
    __half* ot  = (__half*)sym(g_ot);
    __half* wph = (__half*)sym(g_wph);

    // prep
    w3t_kernel<<<dim3(1024, 3), 256>>>(w3q, w3k, w3v);
    weff2<<<dim3(8, 8, 9), 256>>>(w1q, w1k, w1v);
    conv_wproj<<<1024, 256>>>(wproj);
    conv_x<<<Bb*Nn*Cc/512, 256>>>(x);

    // QKV (fused circular shift): [3C x N]
    gemm_qkv<<<dim3(Nn/128, K3/128, Bb), 256, G1_SMEM>>>();
    vtrans<<<dim3(Nn/32, Cc/32, Bb), dim3(32, 8)>>>();

    // scores: S[c,d] = (1/C) * q . k
    {
        G1Args a = {};
        a.A = qkv; a.B = qkv + (size_t)512*Nn;
        a.sA = (long long)K3 * Nn; a.sB = (long long)K3 * Nn; a.sC = (long long)Cc * Cc;
        a.lda = Nn; a.ldb = Nn; a.ldc = Cc; a.K = Nn;
        a.Cf = Sf; a.Ch = nullptr; a.bias = nullptr; a.scale = 1.0f / (float)Cc;
        gemm1<<<dim3(Cc/128, Cc/128, Bb), 256, G1_SMEM>>>(a);
    }
    softmax_p<<<Bb*Cc, 256>>>();

    // PV: Ot[n,c] = sum_d vt[n,d] * P[c,d]
    {
        G1Args a = {};
        a.A = vt; a.B = pp;
        a.sA = (long long)Nn * Cc; a.sB = (long long)Cc * Cc; a.sC = (long long)Nn * Cc;
        a.lda = Cc; a.ldb = Cc; a.ldc = Cc; a.K = Cc;
        a.Cf = nullptr; a.Ch = ot; a.bias = nullptr; a.scale = 1.f;
        gemm1<<<dim3(Cc/128, Nn/128, Bb), 256, G1_SMEM>>>(a);
    }

    // proj: y[n,o] = sum_c Ot[n,c] * wproj[o,c] + bias[o]
    {
        G1Args a = {};
        a.A = ot; a.B = wph;
        a.sA = (long long)Nn * Cc; a.sB = 0; a.sC = (long long)Nn * Cc;
        a.lda = Cc; a.ldb = Cc; a.ldc = Cc; a.K = Cc;
        a.Cf = y; a.Ch = nullptr; a.bias = bproj; a.scale = 1.f;
        gemm1<<<dim3(Cc/128, Nn/128, Bb), 256, G1_SMEM>>>(a);
    }
}

// round 7
// speedup vs baseline: 7.2124x; 1.0826x over previous
#include <cuda_runtime.h>
#include <cuda_fp16.h>
#include <cstdint>

#define Bb 16
#define Nn 2048
#define Cc 512
#define K3 1536

// ---------------- device scratch ----------------
__device__ float  g_w3t [9*512*512];   // [br*3+t][o][i]
__device__ __half g_wh  [1536*1536];   // fp16 Weff [br*512+o][t*512+c]
__device__ __half g_wph [512*512];     // fp16 wproj
__device__ __half g_xh  [16777216];    // [b][n][c] fp16 x
__device__ __half g_qkv [50331648];    // [b][3C][N]
__device__ __half g_vt  [16777216];    // [b][n][d]
__device__ float  g_S   [4194304];     // [b][c][d]
__device__ __half g_p   [4194304];     // softmax(S) fp16
__device__ __half g_ot  [16777216];    // [b][n][c]

// ---------------- PTX helpers ----------------
__device__ __forceinline__ uint32_t s2u(const void* p){
    uint32_t a; asm("{ .reg .u64 t; cvta.to.shared.u64 t, %1; cvt.u32.u64 %0, t; }" : "=r"(a) : "l"(p)); return a;
}
__device__ __forceinline__ void cpa16(uint32_t d, const void* s){
    asm volatile("cp.async.cg.shared.global [%0], [%1], 16;" :: "r"(d), "l"(s));
}
__device__ __forceinline__ void cp_commit(){ asm volatile("cp.async.commit_group;"); }
__device__ __forceinline__ void cp_wait1(){ asm volatile("cp.async.wait_group 1;"); }
__device__ __forceinline__ void cp_wait0(){ asm volatile("cp.async.wait_group 0;"); }
__device__ __forceinline__ void ldsm4(uint32_t& r0, uint32_t& r1, uint32_t& r2, uint32_t& r3, uint32_t a){
    asm volatile("ldmatrix.sync.aligned.m8n8.x4.shared.b16 {%0,%1,%2,%3}, [%4];"
        : "=r"(r0), "=r"(r1), "=r"(r2), "=r"(r3) : "r"(a));
}
__device__ __forceinline__ void mma16816(float* d, const uint32_t* a, uint32_t b0, uint32_t b1){
    asm volatile("mma.sync.aligned.m16n8k16.row.col.f32.f16.f16.f32 "
        "{%0,%1,%2,%3}, {%4,%5,%6,%7}, {%8,%9}, {%0,%1,%2,%3};"
        : "+f"(d[0]), "+f"(d[1]), "+f"(d[2]), "+f"(d[3])
        : "r"(a[0]), "r"(a[1]), "r"(a[2]), "r"(a[3]), "r"(b0), "r"(b1));
}

#define ROWB 80u
#define MATB 10240u

// =====================================================================
// gemm_qkv: QKV with x-dedup (3 shifts read from one smem x tile) and
// CTA tile M=128 x N=256. K loop = 16 chunks of c=32; per chunk the
// loader brings 3 Weff t-slices (128x32 each) + x rows [n0-1, n0+256].
// Shift t realized as +t row offset in B ldmatrix. 1 CTA/SM.
// =====================================================================
#define QA_OFF  0u            // 3 A slices: t*MATB, 128 rows x 80B
#define QB_OFF  30720u        // x tile: 258 rows x 80B = 20640
#define QBUF    51360u
#define Q_SMEM  (2*51360)

__global__ __launch_bounds__(256, 1) void gemm_qkv() {
    extern __shared__ char smem[];
    uint32_t sb = s2u(smem);
    const int tid  = threadIdx.x;
    const int lane = tid & 31;
    const int wid  = tid >> 5;

    const int b  = blockIdx.z;
    const int m0 = blockIdx.y * 128;      // output row block (of 3C)
    const int n0 = blockIdx.x * 256;      // output col block (of N)
    const __half* Ap = g_wh + (size_t)m0 * K3;
    const __half* Xb = g_xh + (size_t)b * Nn * Cc;

    const int NK = Cc >> 5;               // 16 c-chunks

    auto load_chunk = [&](int kc) {
        uint32_t base = sb + (uint32_t)(kc & 1) * QBUF;
        int c0 = kc << 5;
        // A: 3 t-slices, 128 rows x 4 units each -> 1536 units, 6 per thread
        #pragma unroll
        for (int it = 0; it < 6; it++) {
            int u  = tid + it * 256;
            int sl = u >> 9;               // t slice
            int rm = u & 511;
            int r  = rm >> 2, cu = rm & 3;
            cpa16(base + QA_OFF + (uint32_t)sl*MATB + (uint32_t)r*ROWB + (uint32_t)cu*16u,
                  Ap + (size_t)r * K3 + sl*512 + c0 + cu*8);
        }
        // B: 258 rows x 4 units = 1032 units
        #pragma unroll
        for (int it = 0; it < 4; it++) {
            int u = tid + it * 256;        // 0..1023
            int r = u >> 2, cu = u & 3;
            int n = n0 + r - 1;
            if (n < 0) n += Nn; else if (n >= Nn) n -= Nn;
            cpa16(base + QB_OFF + (uint32_t)r*ROWB + (uint32_t)cu*16u,
                  Xb + (size_t)n * Cc + c0 + cu*8);
        }
        if (tid < 8) {                     // tail units 1024..1031
            int u = 1024 + tid;
            int r = u >> 2, cu = u & 3;
            int n = n0 + r - 1;
            if (n >= Nn) n -= Nn;
            cpa16(base + QB_OFF + (uint32_t)r*ROWB + (uint32_t)cu*16u,
                  Xb + (size_t)n * Cc + c0 + cu*8);
        }
        cp_commit();
    };

    float acc[2][16][4];
    #pragma unroll
    for (int i = 0; i < 2; i++)
        #pragma unroll
        for (int j = 0; j < 16; j++)
            #pragma unroll
            for (int q = 0; q < 4; q++) acc[i][j][q] = 0.f;

    const int m0w = (wid >> 1) * 32;       // 4 M warp-groups
    const int n0w = (wid & 1) * 128;       // 2 N warp-groups
    const int l16 = lane & 15, hi = lane >> 4;

    load_chunk(0);
    for (int kc = 0; kc < NK; kc++) {
        if (kc + 1 < NK) { load_chunk(kc + 1); cp_wait1(); }
        else             { cp_wait0(); }
        __syncthreads();
        uint32_t base = sb + (uint32_t)(kc & 1) * QBUF;
        #pragma unroll
        for (int t = 0; t < 3; t++) {
            uint32_t aB = base + QA_OFF + (uint32_t)t*MATB + (uint32_t)(m0w + l16)*ROWB + (uint32_t)hi*16u;
            uint32_t bB = base + QB_OFF + (uint32_t)(n0w + l16 + t)*ROWB + (uint32_t)hi*16u;
            #pragma unroll
            for (int ks = 0; ks < 2; ks++) {
                uint32_t koff = (uint32_t)ks * 32u;
                uint32_t av[2][4], bv[8][4];
                ldsm4(av[0][0], av[0][1], av[0][2], av[0][3], aB + koff);
                ldsm4(av[1][0], av[1][1], av[1][2], av[1][3], aB + 16*ROWB + koff);
                #pragma unroll
                for (int nt = 0; nt < 8; nt++)
                    ldsm4(bv[nt][0], bv[nt][1], bv[nt][2], bv[nt][3],
                          bB + (uint32_t)nt*16*ROWB + koff);
                #pragma unroll
                for (int mi = 0; mi < 2; mi++) {
                    #pragma unroll
                    for (int nj = 0; nj < 16; nj++) {
                        int nt = nj >> 1, sel = nj & 1;
                        uint32_t b0 = sel ? bv[nt][1] : bv[nt][0];
                        uint32_t b1 = sel ? bv[nt][3] : bv[nt][2];
                        mma16816(acc[mi][nj], av[mi], b0, b1);
                    }
                }
            }
        }
        __syncthreads();
    }

    const int rowBase = m0 + m0w + (lane >> 2);
    const int colBase = n0 + n0w + (lane & 3) * 2;
    __half* C = g_qkv + (size_t)b * K3 * Nn;
    #pragma unroll
    for (int mi = 0; mi < 2; mi++) {
        #pragma unroll
        for (int nj = 0; nj < 16; nj++) {
            int c = colBase + nj * 8;
            #pragma unroll
            for (int half = 0; half < 2; half++) {
                int r = rowBase + mi * 16 + half * 8;
                *(__half2*)(C + (size_t)r * Nn + c) =
                    __halves2half2(__float2half_rn(acc[mi][nj][half*2]),
                                   __float2half_rn(acc[mi][nj][half*2+1]));
            }
        }
    }
}

// =====================================================================
// gemm1: generic plain-fp16 GEMM (CTA 128x128, warps 4Mx2N). D = A*B^T.
// =====================================================================
#define BUF1 20480u
#define G1_SMEM (2*20480)

struct G1Args {
    const __half* A; const __half* B;
    long long sA, sB, sC;
    int lda, ldb, ldc, K;
    float* Cf; __half* Ch;
    const float* bias;
    float scale;
};

__global__ __launch_bounds__(256, 2) void gemm1(const G1Args g) {
    extern __shared__ char smem[];
    uint32_t sb = s2u(smem);
    const int tid  = threadIdx.x;
    const int lane = tid & 31;
    const int wid  = tid >> 5;

    const int b  = blockIdx.z;
    const int m0 = blockIdx.y * 128;
    const int n0 = blockIdx.x * 128;
    const __half* Ap = g.A + (long long)b * g.sA + (long long)m0 * g.lda;
    const __half* Bp = g.B + (long long)b * g.sB + (long long)n0 * g.ldb;

    const int NK = g.K >> 5;

    auto load_chunk = [&](int kc) {
        uint32_t base = sb + (uint32_t)(kc & 1) * BUF1;
        int ko = kc << 5;
        #pragma unroll
        for (int it = 0; it < 2; it++) {
            int u = tid + it * 256;
            int r = u >> 2, cu = u & 3;
            uint32_t off = (uint32_t)r * ROWB + (uint32_t)cu * 16u;
            cpa16(base + off,        Ap + (size_t)r * g.lda + ko + cu * 8);
            cpa16(base + MATB + off, Bp + (size_t)r * g.ldb + ko + cu * 8);
        }
        cp_commit();
    };

    float acc[2][8][4];
    #pragma unroll
    for (int i = 0; i < 2; i++)
        #pragma unroll
        for (int j = 0; j < 8; j++)
            #pragma unroll
            for (int q = 0; q < 4; q++) acc[i][j][q] = 0.f;

    const int m0w = (wid >> 1) * 32;
    const int n0w = (wid & 1) * 64;
    const int l16 = lane & 15, hi = lane >> 4;

    load_chunk(0);
    for (int kc = 0; kc < NK; kc++) {
        if (kc + 1 < NK) { load_chunk(kc + 1); cp_wait1(); }
        else             { cp_wait0(); }
        __syncthreads();
        uint32_t base = sb + (uint32_t)(kc & 1) * BUF1;
        uint32_t aAddr = base + (uint32_t)(m0w + l16) * ROWB + (uint32_t)hi * 16u;
        uint32_t bAddr = base + MATB + (uint32_t)(n0w + l16) * ROWB + (uint32_t)hi * 16u;
        #pragma unroll
        for (int ks = 0; ks < 2; ks++) {
            uint32_t koff = (uint32_t)ks * 32u;
            uint32_t av[2][4], bv[4][4];
            ldsm4(av[0][0], av[0][1], av[0][2], av[0][3], aAddr + koff);
            ldsm4(av[1][0], av[1][1], av[1][2], av[1][3], aAddr + 16*ROWB + koff);
            #pragma unroll
            for (int nt = 0; nt < 4; nt++)
                ldsm4(bv[nt][0], bv[nt][1], bv[nt][2], bv[nt][3], bAddr + (uint32_t)nt*16*ROWB + koff);
            #pragma unroll
            for (int mi = 0; mi < 2; mi++) {
                #pragma unroll
                for (int nj = 0; nj < 8; nj++) {
                    int nt = nj >> 1, sel = nj & 1;
                    uint32_t b0 = sel ? bv[nt][1] : bv[nt][0];
                    uint32_t b1 = sel ? bv[nt][3] : bv[nt][2];
                    mma16816(acc[mi][nj], av[mi], b0, b1);
                }
            }
        }
        __syncthreads();
    }

    const int rowBase = m0 + m0w + (lane >> 2);
    const int colBase = n0 + n0w + (lane & 3) * 2;
    if (g.Cf) {
        float* C = g.Cf + (long long)b * g.sC;
        #pragma unroll
        for (int mi = 0; mi < 2; mi++) {
            #pragma unroll
            for (int nj = 0; nj < 8; nj++) {
                int c = colBase + nj * 8;
                #pragma unroll
                for (int half = 0; half < 2; half++) {
                    int r = rowBase + mi * 16 + half * 8;
                    float2 v;
                    v.x = acc[mi][nj][half*2 + 0] * g.scale;
                    v.y = acc[mi][nj][half*2 + 1] * g.scale;
                    if (g.bias) { v.x += g.bias[c]; v.y += g.bias[c + 1]; }
                    *(float2*)(C + (long long)r * g.ldc + c) = v;
                }
            }
        }
    } else {
        __half* C = g.Ch + (long long)b * g.sC;
        #pragma unroll
        for (int mi = 0; mi < 2; mi++) {
            #pragma unroll
            for (int nj = 0; nj < 8; nj++) {
                int c = colBase + nj * 8;
                #pragma unroll
                for (int half = 0; half < 2; half++) {
                    int r = rowBase + mi * 16 + half * 8;
                    *(__half2*)(C + (long long)r * g.ldc + c) =
                        __halves2half2(__float2half_rn(acc[mi][nj][half*2]),
                                       __float2half_rn(acc[mi][nj][half*2+1]));
                }
            }
        }
    }
}

// ---------------- w3 transpose ----------------
__global__ __launch_bounds__(256) void w3t_kernel(const float* __restrict__ w3q,
                                                  const float* __restrict__ w3k,
                                                  const float* __restrict__ w3v) {
    int oi = blockIdx.x * 256 + threadIdx.x;
    int br = blockIdx.y;
    const float* w3 = br == 0 ? w3q : br == 1 ? w3k : w3v;
    float a = w3[(size_t)oi*3 + 0];
    float b = w3[(size_t)oi*3 + 1];
    float c = w3[(size_t)oi*3 + 2];
    g_w3t[(size_t)(br*3 + 0)*262144 + oi] = a;
    g_w3t[(size_t)(br*3 + 1)*262144 + oi] = b;
    g_w3t[(size_t)(br*3 + 2)*262144 + oi] = c;
}

// ---------------- weff (fp32 SIMT, fp16 output) ----------------
__global__ __launch_bounds__(256) void weff2(const float* __restrict__ w1q,
                                             const float* __restrict__ w1k,
                                             const float* __restrict__ w1v) {
    int z = blockIdx.z;
    int br = z / 3, t = z - br*3;
    const float* A  = g_w3t + (size_t)z * 262144;
    const float* w1 = br == 0 ? w1q : br == 1 ? w1k : w1v;
    int n0 = blockIdx.x * 64, m0 = blockIdx.y * 64;
    __shared__ float As[64][17];
    __shared__ float Bs[16][64];
    int tid = threadIdx.x;
    int tx = tid & 15, ty = tid >> 4;
    float acc[4][4] = {};
    for (int k0 = 0; k0 < 512; k0 += 16) {
        {
            int kk = tid & 15, mmb = tid >> 4;
            #pragma unroll
            for (int j = 0; j < 4; j++) {
                int mm = mmb + j*16;
                As[mm][kk] = A[(size_t)(m0+mm)*512 + k0 + kk];
            }
        }
        {
            int nn = tid & 63, kkb = tid >> 6;
            #pragma unroll
            for (int j = 0; j < 4; j++) {
                int kk = kkb + j*4;
                Bs[kk][nn] = w1[(size_t)(k0+kk)*512 + n0 + nn];
            }
        }
        __syncthreads();
        #pragma unroll
        for (int kk = 0; kk < 16; kk++) {
            float a[4];
            #pragma unroll
            for (int i = 0; i < 4; i++) a[i] = As[ty*4+i][kk];
            float4 bv = *(const float4*)&Bs[kk][tx*4];
            float bf[4] = {bv.x, bv.y, bv.z, bv.w};
            #pragma unroll
            for (int i = 0; i < 4; i++)
                #pragma unroll
                for (int j = 0; j < 4; j++) acc[i][j] += a[i]*bf[j];
        }
        __syncthreads();
    }
    #pragma unroll
    for (int i = 0; i < 4; i++) {
        int o = m0 + ty*4 + i;
        #pragma unroll
        for (int j = 0; j < 4; j++) {
            int c = n0 + tx*4 + j;
            g_wh[(size_t)(br*512 + o)*K3 + t*512 + c] = __float2half_rn(acc[i][j]);
        }
    }
}

// ---------------- converts ----------------
__global__ __launch_bounds__(256) void conv_wproj(const float* __restrict__ w) {
    size_t i = (size_t)blockIdx.x * 256 + threadIdx.x;
    g_wph[i] = __float2half_rn(w[i]);
}
__global__ __launch_bounds__(256) void conv_x(const float* __restrict__ x) {
    size_t i = (size_t)blockIdx.x * 256 + threadIdx.x;
    float2 v = *(const float2*)(x + i * 2);
    *(__half2*)(g_xh + i * 2) = __halves2half2(__float2half_rn(v.x), __float2half_rn(v.y));
}

// ---------------- v transpose: vt[b][n][d] = qkv[b][1024+d][n] ----------------
__global__ __launch_bounds__(256) void vtrans() {
    __shared__ __half t0[32][33];
    int b = blockIdx.z;
    int n0 = blockIdx.x * 32, d0 = blockIdx.y * 32;
    int tx = threadIdx.x, ty = threadIdx.y;
    const __half* sh = g_qkv + (size_t)b*K3*Nn + (size_t)(1024 + d0)*Nn + n0;
    #pragma unroll
    for (int i = 0; i < 32; i += 8)
        t0[ty+i][tx] = sh[(size_t)(ty+i)*Nn + tx];
    __syncthreads();
    __half* dh = g_vt + (size_t)b*Nn*Cc;
    #pragma unroll
    for (int i = 0; i < 32; i += 8)
        dh[(size_t)(n0+ty+i)*Cc + d0 + tx] = t0[tx][ty+i];
}

// ---------------- softmax -> fp16 P ----------------
__global__ __launch_bounds__(256) void softmax_p() {
    size_t row = blockIdx.x;
    const float* p = g_S + row * Cc;
    int tid = threadIdx.x;
    float v0 = p[tid], v1 = p[tid + 256];
    float m = fmaxf(v0, v1);
    __shared__ float red[8];
    #pragma unroll
    for (int o = 16; o > 0; o >>= 1) m = fmaxf(m, __shfl_xor_sync(0xffffffffu, m, o));
    if ((tid & 31) == 0) red[tid >> 5] = m;
    __syncthreads();
    float mm = red[0];
    #pragma unroll
    for (int i = 1; i < 8; i++) mm = fmaxf(mm, red[i]);
    float e0 = __expf(v0 - mm), e1 = __expf(v1 - mm);
    float s = e0 + e1;
    #pragma unroll
    for (int o = 16; o > 0; o >>= 1) s += __shfl_xor_sync(0xffffffffu, s, o);
    __syncthreads();
    if ((tid & 31) == 0) red[tid >> 5] = s;
    __syncthreads();
    float ss = 0.f;
    #pragma unroll
    for (int i = 0; i < 8; i++) ss += red[i];
    float inv = 1.0f / ss;
    g_p[row*Cc + tid]       = __float2half_rn(e0 * inv);
    g_p[row*Cc + tid + 256] = __float2half_rn(e1 * inv);
}

// ---------------- launch ----------------
static void* sym(const void* s) { void* p = nullptr; cudaGetSymbolAddress(&p, s); return p; }

extern "C" void kernel_launch(void* const* d_in, const int* in_sizes, int n_in,
                              void* d_out, int out_size) {
    const float* x     = (const float*)d_in[0];
    const float* w1q   = (const float*)d_in[1];
    const float* w3q   = (const float*)d_in[2];
    const float* w1k   = (const float*)d_in[3];
    const float* w3k   = (const float*)d_in[4];
    const float* w1v   = (const float*)d_in[5];
    const float* w3v   = (const float*)d_in[6];
    const float* wproj = (const float*)d_in[7];
    const float* bproj = (const float*)d_in[8];
    float* y = (float*)d_out;

    cudaFuncSetAttribute(gemm_qkv, cudaFuncAttributeMaxDynamicSharedMemorySize, Q_SMEM);
    cudaFuncSetAttribute(gemm1,    cudaFuncAttributeMaxDynamicSharedMemorySize, G1_SMEM);

    __half* qkv = (__half*)sym(g_qkv);
    __half* vt  = (__half*)sym(g_vt);
    float*  Sf  = (float*) sym(g_S);
    __half* pp  = (__half*)sym(g_p);
    __half* ot  = (__half*)sym(g_ot);
    __half* wph = (__half*)sym(g_wph);

    // prep
    w3t_kernel<<<dim3(1024, 3), 256>>>(w3q, w3k, w3v);
    weff2<<<dim3(8, 8, 9), 256>>>(w1q, w1k, w1v);
    conv_wproj<<<1024, 256>>>(wproj);
    conv_x<<<Bb*Nn*Cc/512, 256>>>(x);

    // QKV (x-dedup + 128x256 tile): [3C x N]
    gemm_qkv<<<dim3(Nn/256, K3/128, Bb), 256, Q_SMEM>>>();
    vtrans<<<dim3(Nn/32, Cc/32, Bb), dim3(32, 8)>>>();

    // scores: S[c,d] = (1/C) * q . k
    {
        G1Args a = {};
        a.A = qkv; a.B = qkv + (size_t)512*Nn;
        a.sA = (long long)K3 * Nn; a.sB = (long long)K3 * Nn; a.sC = (long long)Cc * Cc;
        a.lda = Nn; a.ldb = Nn; a.ldc = Cc; a.K = Nn;
        a.Cf = Sf; a.Ch = nullptr; a.bias = nullptr; a.scale = 1.0f / (float)Cc;
        gemm1<<<dim3(Cc/128, Cc/128, Bb), 256, G1_SMEM>>>(a);
    }
    softmax_p<<<Bb*Cc, 256>>>();

    // PV: Ot[n,c] = sum_d vt[n,d] * P[c,d]
    {
        G1Args a = {};
        a.A = vt; a.B = pp;
        a.sA = (long long)Nn * Cc; a.sB = (long long)Cc * Cc; a.sC = (long long)Nn * Cc;
        a.lda = Cc; a.ldb = Cc; a.ldc = Cc; a.K = Cc;
        a.Cf = nullptr; a.Ch = ot; a.bias = nullptr; a.scale = 1.f;
        gemm1<<<dim3(Cc/128, Nn/128, Bb), 256, G1_SMEM>>>(a);
    }

    // proj: y[n,o] = sum_c Ot[n,c] * wproj[o,c] + bias[o]
    {
        G1Args a = {};
        a.A = ot; a.B = wph;
        a.sA = (long long)Nn * Cc; a.sB = 0; a.sC = (long long)Nn * Cc;
        a.lda = Cc; a.ldb = Cc; a.ldc = Cc; a.K = Cc;
        a.Cf = y; a.Ch = nullptr; a.bias = bproj; a.scale = 1.f;
        gemm1<<<dim3(Cc/128, Nn/128, Bb), 256, G1_SMEM>>>(a);
    }
}

// round 8
// speedup vs baseline: 7.3619x; 1.0207x over previous
#include <cuda_runtime.h>
#include <cuda_fp16.h>
#include <cstdint>

#define Bb 16
#define Nn 2048
#define Cc 512
#define K3 1536

// ---------------- device scratch ----------------
__device__ __half g_wh  [1536*1536];   // fp16 Weff [br*512+o][t*512+c]
__device__ __half g_wph [512*512];     // fp16 wproj
__device__ __half g_xh  [16777216];    // [b][n][c] fp16 x
__device__ __half g_qkv [50331648];    // [b][3C][N]
__device__ __half g_vt  [16777216];    // [b][n][d]
__device__ float  g_S   [4194304];     // [b][c][d]
__device__ __half g_p   [4194304];     // softmax(S) fp16
__device__ __half g_ot  [16777216];    // [b][n][c]

// ---------------- PTX helpers ----------------
__device__ __forceinline__ uint32_t s2u(const void* p){
    uint32_t a; asm("{ .reg .u64 t; cvta.to.shared.u64 t, %1; cvt.u32.u64 %0, t; }" : "=r"(a) : "l"(p)); return a;
}
__device__ __forceinline__ void cpa16(uint32_t d, const void* s){
    asm volatile("cp.async.cg.shared.global [%0], [%1], 16;" :: "r"(d), "l"(s));
}
__device__ __forceinline__ void cp_commit(){ asm volatile("cp.async.commit_group;"); }
__device__ __forceinline__ void cp_wait1(){ asm volatile("cp.async.wait_group 1;"); }
__device__ __forceinline__ void cp_wait0(){ asm volatile("cp.async.wait_group 0;"); }
__device__ __forceinline__ void ldsm4(uint32_t& r0, uint32_t& r1, uint32_t& r2, uint32_t& r3, uint32_t a){
    asm volatile("ldmatrix.sync.aligned.m8n8.x4.shared.b16 {%0,%1,%2,%3}, [%4];"
        : "=r"(r0), "=r"(r1), "=r"(r2), "=r"(r3) : "r"(a));
}
__device__ __forceinline__ void mma16816(float* d, const uint32_t* a, uint32_t b0, uint32_t b1){
    asm volatile("mma.sync.aligned.m16n8k16.row.col.f32.f16.f16.f32 "
        "{%0,%1,%2,%3}, {%4,%5,%6,%7}, {%8,%9}, {%0,%1,%2,%3};"
        : "+f"(d[0]), "+f"(d[1]), "+f"(d[2]), "+f"(d[3])
        : "r"(a[0]), "r"(a[1]), "r"(a[2]), "r"(a[3]), "r"(b0), "r"(b1));
}

#define ROWB 80u
#define MATB 10240u

// =====================================================================
// gemm_qkv: QKV, x-dedup, CTA M=128 x N=256, 3-stage single-sync pipe.
// =====================================================================
#define QA_OFF  0u
#define QB_OFF  30720u
#define QBUF    51360u
#define Q_SMEM  (3*51360)

__global__ __launch_bounds__(256, 1) void gemm_qkv() {
    extern __shared__ char smem[];
    uint32_t sb = s2u(smem);
    const int tid  = threadIdx.x;
    const int lane = tid & 31;
    const int wid  = tid >> 5;

    const int b  = blockIdx.z;
    const int m0 = blockIdx.y * 128;
    const int n0 = blockIdx.x * 256;
    const __half* Ap = g_wh + (size_t)m0 * K3;
    const __half* Xb = g_xh + (size_t)b * Nn * Cc;

    const int NK = Cc >> 5;   // 16

    auto load_chunk = [&](int kc) {
        uint32_t base = sb + (uint32_t)(kc % 3) * QBUF;
        int c0 = kc << 5;
        #pragma unroll
        for (int it = 0; it < 6; it++) {
            int u  = tid + it * 256;
            int sl = u >> 9;
            int rm = u & 511;
            int r  = rm >> 2, cu = rm & 3;
            cpa16(base + QA_OFF + (uint32_t)sl*MATB + (uint32_t)r*ROWB + (uint32_t)cu*16u,
                  Ap + (size_t)r * K3 + sl*512 + c0 + cu*8);
        }
        #pragma unroll
        for (int it = 0; it < 4; it++) {
            int u = tid + it * 256;
            int r = u >> 2, cu = u & 3;
            int n = n0 + r - 1;
            if (n < 0) n += Nn; else if (n >= Nn) n -= Nn;
            cpa16(base + QB_OFF + (uint32_t)r*ROWB + (uint32_t)cu*16u,
                  Xb + (size_t)n * Cc + c0 + cu*8);
        }
        if (tid < 8) {
            int u = 1024 + tid;
            int r = u >> 2, cu = u & 3;
            int n = n0 + r - 1;
            if (n >= Nn) n -= Nn;
            cpa16(base + QB_OFF + (uint32_t)r*ROWB + (uint32_t)cu*16u,
                  Xb + (size_t)n * Cc + c0 + cu*8);
        }
        cp_commit();
    };

    float acc[2][16][4];
    #pragma unroll
    for (int i = 0; i < 2; i++)
        #pragma unroll
        for (int j = 0; j < 16; j++)
            #pragma unroll
            for (int q = 0; q < 4; q++) acc[i][j][q] = 0.f;

    const int m0w = (wid >> 1) * 32;
    const int n0w = (wid & 1) * 128;
    const int l16 = lane & 15, hi = lane >> 4;

    load_chunk(0);
    load_chunk(1);
    for (int kc = 0; kc < NK; kc++) {
        if (kc + 1 < NK) cp_wait1(); else cp_wait0();
        __syncthreads();
        if (kc + 2 < NK) load_chunk(kc + 2);
        uint32_t base = sb + (uint32_t)(kc % 3) * QBUF;
        #pragma unroll
        for (int t = 0; t < 3; t++) {
            uint32_t aB = base + QA_OFF + (uint32_t)t*MATB + (uint32_t)(m0w + l16)*ROWB + (uint32_t)hi*16u;
            uint32_t bB = base + QB_OFF + (uint32_t)(n0w + l16 + t)*ROWB + (uint32_t)hi*16u;
            #pragma unroll
            for (int ks = 0; ks < 2; ks++) {
                uint32_t koff = (uint32_t)ks * 32u;
                uint32_t av[2][4], bv[8][4];
                ldsm4(av[0][0], av[0][1], av[0][2], av[0][3], aB + koff);
                ldsm4(av[1][0], av[1][1], av[1][2], av[1][3], aB + 16*ROWB + koff);
                #pragma unroll
                for (int nt = 0; nt < 8; nt++)
                    ldsm4(bv[nt][0], bv[nt][1], bv[nt][2], bv[nt][3],
                          bB + (uint32_t)nt*16*ROWB + koff);
                #pragma unroll
                for (int mi = 0; mi < 2; mi++) {
                    #pragma unroll
                    for (int nj = 0; nj < 16; nj++) {
                        int nt = nj >> 1, sel = nj & 1;
                        uint32_t b0 = sel ? bv[nt][1] : bv[nt][0];
                        uint32_t b1 = sel ? bv[nt][3] : bv[nt][2];
                        mma16816(acc[mi][nj], av[mi], b0, b1);
                    }
                }
            }
        }
    }

    const int rowBase = m0 + m0w + (lane >> 2);
    const int colBase = n0 + n0w + (lane & 3) * 2;
    __half* C = g_qkv + (size_t)b * K3 * Nn;
    #pragma unroll
    for (int mi = 0; mi < 2; mi++) {
        #pragma unroll
        for (int nj = 0; nj < 16; nj++) {
            int c = colBase + nj * 8;
            #pragma unroll
            for (int half = 0; half < 2; half++) {
                int r = rowBase + mi * 16 + half * 8;
                *(__half2*)(C + (size_t)r * Nn + c) =
                    __halves2half2(__float2half_rn(acc[mi][nj][half*2]),
                                   __float2half_rn(acc[mi][nj][half*2+1]));
            }
        }
    }
}

// =====================================================================
// gemm1: generic plain-fp16 GEMM, 3-stage single-sync, 2 CTAs/SM.
// =====================================================================
#define BUF1 20480u
#define G1_SMEM (3*20480)

struct G1Args {
    const __half* A; const __half* B;
    long long sA, sB, sC;
    int lda, ldb, ldc, K;
    float* Cf; __half* Ch;
    const float* bias;
    float scale;
};

__global__ __launch_bounds__(256, 2) void gemm1(const G1Args g) {
    extern __shared__ char smem[];
    uint32_t sb = s2u(smem);
    const int tid  = threadIdx.x;
    const int lane = tid & 31;
    const int wid  = tid >> 5;

    const int b  = blockIdx.z;
    const int m0 = blockIdx.y * 128;
    const int n0 = blockIdx.x * 128;
    const __half* Ap = g.A + (long long)b * g.sA + (long long)m0 * g.lda;
    const __half* Bp = g.B + (long long)b * g.sB + (long long)n0 * g.ldb;

    const int NK = g.K >> 5;

    auto load_chunk = [&](int kc) {
        uint32_t base = sb + (uint32_t)(kc % 3) * BUF1;
        int ko = kc << 5;
        #pragma unroll
        for (int it = 0; it < 2; it++) {
            int u = tid + it * 256;
            int r = u >> 2, cu = u & 3;
            uint32_t off = (uint32_t)r * ROWB + (uint32_t)cu * 16u;
            cpa16(base + off,        Ap + (size_t)r * g.lda + ko + cu * 8);
            cpa16(base + MATB + off, Bp + (size_t)r * g.ldb + ko + cu * 8);
        }
        cp_commit();
    };

    float acc[2][8][4];
    #pragma unroll
    for (int i = 0; i < 2; i++)
        #pragma unroll
        for (int j = 0; j < 8; j++)
            #pragma unroll
            for (int q = 0; q < 4; q++) acc[i][j][q] = 0.f;

    const int m0w = (wid >> 1) * 32;
    const int n0w = (wid & 1) * 64;
    const int l16 = lane & 15, hi = lane >> 4;

    load_chunk(0);
    load_chunk(1);
    for (int kc = 0; kc < NK; kc++) {
        if (kc + 1 < NK) cp_wait1(); else cp_wait0();
        __syncthreads();
        if (kc + 2 < NK) load_chunk(kc + 2);
        uint32_t base = sb + (uint32_t)(kc % 3) * BUF1;
        uint32_t aAddr = base + (uint32_t)(m0w + l16) * ROWB + (uint32_t)hi * 16u;
        uint32_t bAddr = base + MATB + (uint32_t)(n0w + l16) * ROWB + (uint32_t)hi * 16u;
        #pragma unroll
        for (int ks = 0; ks < 2; ks++) {
            uint32_t koff = (uint32_t)ks * 32u;
            uint32_t av[2][4], bv[4][4];
            ldsm4(av[0][0], av[0][1], av[0][2], av[0][3], aAddr + koff);
            ldsm4(av[1][0], av[1][1], av[1][2], av[1][3], aAddr + 16*ROWB + koff);
            #pragma unroll
            for (int nt = 0; nt < 4; nt++)
                ldsm4(bv[nt][0], bv[nt][1], bv[nt][2], bv[nt][3], bAddr + (uint32_t)nt*16*ROWB + koff);
            #pragma unroll
            for (int mi = 0; mi < 2; mi++) {
                #pragma unroll
                for (int nj = 0; nj < 8; nj++) {
                    int nt = nj >> 1, sel = nj & 1;
                    uint32_t b0 = sel ? bv[nt][1] : bv[nt][0];
                    uint32_t b1 = sel ? bv[nt][3] : bv[nt][2];
                    mma16816(acc[mi][nj], av[mi], b0, b1);
                }
            }
        }
    }

    const int rowBase = m0 + m0w + (lane >> 2);
    const int colBase = n0 + n0w + (lane & 3) * 2;
    if (g.Cf) {
        float* C = g.Cf + (long long)b * g.sC;
        #pragma unroll
        for (int mi = 0; mi < 2; mi++) {
            #pragma unroll
            for (int nj = 0; nj < 8; nj++) {
                int c = colBase + nj * 8;
                #pragma unroll
                for (int half = 0; half < 2; half++) {
                    int r = rowBase + mi * 16 + half * 8;
                    float2 v;
                    v.x = acc[mi][nj][half*2 + 0] * g.scale;
                    v.y = acc[mi][nj][half*2 + 1] * g.scale;
                    if (g.bias) { v.x += g.bias[c]; v.y += g.bias[c + 1]; }
                    *(float2*)(C + (long long)r * g.ldc + c) = v;
                }
            }
        }
    } else {
        __half* C = g.Ch + (long long)b * g.sC;
        #pragma unroll
        for (int mi = 0; mi < 2; mi++) {
            #pragma unroll
            for (int nj = 0; nj < 8; nj++) {
                int c = colBase + nj * 8;
                #pragma unroll
                for (int half = 0; half < 2; half++) {
                    int r = rowBase + mi * 16 + half * 8;
                    *(__half2*)(C + (long long)r * g.ldc + c) =
                        __halves2half2(__float2half_rn(acc[mi][nj][half*2]),
                                       __float2half_rn(acc[mi][nj][half*2+1]));
                }
            }
        }
    }
}

// ---------------- weff: direct strided w3 read, fp16 out ----------------
__global__ __launch_bounds__(256) void weff2(const float* __restrict__ w1q,
                                             const float* __restrict__ w1k,
                                             const float* __restrict__ w1v,
                                             const float* __restrict__ w3q,
                                             const float* __restrict__ w3k,
                                             const float* __restrict__ w3v) {
    int z = blockIdx.z;
    int br = z / 3, t = z - br*3;
    const float* w3 = br == 0 ? w3q : br == 1 ? w3k : w3v;
    const float* w1 = br == 0 ? w1q : br == 1 ? w1k : w1v;
    int n0 = blockIdx.x * 64, m0 = blockIdx.y * 64;
    __shared__ float As[64][17];
    __shared__ float Bs[16][64];
    int tid = threadIdx.x;
    int tx = tid & 15, ty = tid >> 4;
    float acc[4][4] = {};
    for (int k0 = 0; k0 < 512; k0 += 16) {
        {
            int kk = tid & 15, mmb = tid >> 4;
            #pragma unroll
            for (int j = 0; j < 4; j++) {
                int mm = mmb + j*16;
                As[mm][kk] = w3[(size_t)(m0+mm)*1536 + (size_t)(k0+kk)*3 + t];
            }
        }
        {
            int nn = tid & 63, kkb = tid >> 6;
            #pragma unroll
            for (int j = 0; j < 4; j++) {
                int kk = kkb + j*4;
                Bs[kk][nn] = w1[(size_t)(k0+kk)*512 + n0 + nn];
            }
        }
        __syncthreads();
        #pragma unroll
        for (int kk = 0; kk < 16; kk++) {
            float a[4];
            #pragma unroll
            for (int i = 0; i < 4; i++) a[i] = As[ty*4+i][kk];
            float4 bv = *(const float4*)&Bs[kk][tx*4];
            float bf[4] = {bv.x, bv.y, bv.z, bv.w};
            #pragma unroll
            for (int i = 0; i < 4; i++)
                #pragma unroll
                for (int j = 0; j < 4; j++) acc[i][j] += a[i]*bf[j];
        }
        __syncthreads();
    }
    #pragma unroll
    for (int i = 0; i < 4; i++) {
        int o = m0 + ty*4 + i;
        #pragma unroll
        for (int j = 0; j < 4; j++) {
            int c = n0 + tx*4 + j;
            g_wh[(size_t)(br*512 + o)*K3 + t*512 + c] = __float2half_rn(acc[i][j]);
        }
    }
}

// ---------------- converts ----------------
__global__ __launch_bounds__(256) void conv_wproj(const float* __restrict__ w) {
    size_t i = (size_t)blockIdx.x * 256 + threadIdx.x;
    g_wph[i] = __float2half_rn(w[i]);
}
__global__ __launch_bounds__(256) void conv_x(const float* __restrict__ x) {
    size_t i = (size_t)blockIdx.x * 256 + threadIdx.x;
    float2 v = *(const float2*)(x + i * 2);
    *(__half2*)(g_xh + i * 2) = __halves2half2(__float2half_rn(v.x), __float2half_rn(v.y));
}

// ---------------- v transpose ----------------
__global__ __launch_bounds__(256) void vtrans() {
    __shared__ __half t0[32][33];
    int b = blockIdx.z;
    int n0 = blockIdx.x * 32, d0 = blockIdx.y * 32;
    int tx = threadIdx.x, ty = threadIdx.y;
    const __half* sh = g_qkv + (size_t)b*K3*Nn + (size_t)(1024 + d0)*Nn + n0;
    #pragma unroll
    for (int i = 0; i < 32; i += 8)
        t0[ty+i][tx] = sh[(size_t)(ty+i)*Nn + tx];
    __syncthreads();
    __half* dh = g_vt + (size_t)b*Nn*Cc;
    #pragma unroll
    for (int i = 0; i < 32; i += 8)
        dh[(size_t)(n0+ty+i)*Cc + d0 + tx] = t0[tx][ty+i];
}

// ---------------- softmax -> fp16 P ----------------
__global__ __launch_bounds__(256) void softmax_p() {
    size_t row = blockIdx.x;
    const float* p = g_S + row * Cc;
    int tid = threadIdx.x;
    float v0 = p[tid], v1 = p[tid + 256];
    float m = fmaxf(v0, v1);
    __shared__ float red[8];
    #pragma unroll
    for (int o = 16; o > 0; o >>= 1) m = fmaxf(m, __shfl_xor_sync(0xffffffffu, m, o));
    if ((tid & 31) == 0) red[tid >> 5] = m;
    __syncthreads();
    float mm = red[0];
    #pragma unroll
    for (int i = 1; i < 8; i++) mm = fmaxf(mm, red[i]);
    float e0 = __expf(v0 - mm), e1 = __expf(v1 - mm);
    float s = e0 + e1;
    #pragma unroll
    for (int o = 16; o > 0; o >>= 1) s += __shfl_xor_sync(0xffffffffu, s, o);
    __syncthreads();
    if ((tid & 31) == 0) red[tid >> 5] = s;
    __syncthreads();
    float ss = 0.f;
    #pragma unroll
    for (int i = 0; i < 8; i++) ss += red[i];
    float inv = 1.0f / ss;
    g_p[row*Cc + tid]       = __float2half_rn(e0 * inv);
    g_p[row*Cc + tid + 256] = __float2half_rn(e1 * inv);
}

// ---------------- launch ----------------
static void* sym(const void* s) { void* p = nullptr; cudaGetSymbolAddress(&p, s); return p; }

extern "C" void kernel_launch(void* const* d_in, const int* in_sizes, int n_in,
                              void* d_out, int out_size) {
    const float* x     = (const float*)d_in[0];
    const float* w1q   = (const float*)d_in[1];
    const float* w3q   = (const float*)d_in[2];
    const float* w1k   = (const float*)d_in[3];
    const float* w3k   = (const float*)d_in[4];
    const float* w1v   = (const float*)d_in[5];
    const float* w3v   = (const float*)d_in[6];
    const float* wproj = (const float*)d_in[7];
    const float* bproj = (const float*)d_in[8];
    float* y = (float*)d_out;

    cudaFuncSetAttribute(gemm_qkv, cudaFuncAttributeMaxDynamicSharedMemorySize, Q_SMEM);
    cudaFuncSetAttribute(gemm1,    cudaFuncAttributeMaxDynamicSharedMemorySize, G1_SMEM);

    __half* qkv = (__half*)sym(g_qkv);
    __half* vt  = (__half*)sym(g_vt);
    float*  Sf  = (float*) sym(g_S);
    __half* pp  = (__half*)sym(g_p);
    __half* ot  = (__half*)sym(g_ot);
    __half* wph = (__half*)sym(g_wph);

    // prep
    weff2<<<dim3(8, 8, 9), 256>>>(w1q, w1k, w1v, w3q, w3k, w3v);
    conv_wproj<<<1024, 256>>>(wproj);
    conv_x<<<Bb*Nn*Cc/512, 256>>>(x);

    // QKV: [3C x N]
    gemm_qkv<<<dim3(Nn/256, K3/128, Bb), 256, Q_SMEM>>>();
    vtrans<<<dim3(Nn/32, Cc/32, Bb), dim3(32, 8)>>>();

    // scores: S[c,d] = (1/C) * q . k
    {
        G1Args a = {};
        a.A = qkv; a.B = qkv + (size_t)512*Nn;
        a.sA = (long long)K3 * Nn; a.sB = (long long)K3 * Nn; a.sC = (long long)Cc * Cc;
        a.lda = Nn; a.ldb = Nn; a.ldc = Cc; a.K = Nn;
        a.Cf = Sf; a.Ch = nullptr; a.bias = nullptr; a.scale = 1.0f / (float)Cc;
        gemm1<<<dim3(Cc/128, Cc/128, Bb), 256, G1_SMEM>>>(a);
    }
    softmax_p<<<Bb*Cc, 256>>>();

    // PV: Ot[n,c] = sum_d vt[n,d] * P[c,d]
    {
        G1Args a = {};
        a.A = vt; a.B = pp;
        a.sA = (long long)Nn * Cc; a.sB = (long long)Cc * Cc; a.sC = (long long)Nn * Cc;
        a.lda = Cc; a.ldb = Cc; a.ldc = Cc; a.K = Cc;
        a.Cf = nullptr; a.Ch = ot; a.bias = nullptr; a.scale = 1.f;
        gemm1<<<dim3(Cc/128, Nn/128, Bb), 256, G1_SMEM>>>(a);
    }

    // proj: y[n,o] = sum_c Ot[n,c] * wproj[o,c] + bias[o]
    {
        G1Args a = {};
        a.A = ot; a.B = wph;
        a.sA = (long long)Nn * Cc; a.sB = 0; a.sC = (long long)Nn * Cc;
        a.lda = Cc; a.ldb = Cc; a.ldc = Cc; a.K = Cc;
        a.Cf = y; a.Ch = nullptr; a.bias = bproj; a.scale = 1.f;
        gemm1<<<dim3(Cc/128, Nn/128, Bb), 256, G1_SMEM>>>(a);
    }
}